// round 2
// baseline (speedup 1.0000x reference)
#include <cuda_runtime.h>
#include <cstdint>

#define NB 16
#define CC 512
#define CPD 64
#define NN 4096

// scratch (static __device__ — no allocation)
__device__ float g_Q[(size_t)NB * CPD * NN];
__device__ float g_K[(size_t)NB * CPD * NN];
__device__ float g_V[(size_t)NB * CPD * NN];
__device__ float g_P[(size_t)NB * 16 * CPD * CPD]; // energy partials per N-slice
__device__ float g_M[NB * CC * CPD];               // M = Wo @ A

__device__ __forceinline__ void cp_async16(void* smem, const void* gmem) {
    uint32_t s = (uint32_t)__cvta_generic_to_shared(smem);
    asm volatile("cp.async.cg.shared.global [%0], [%1], 16;\n" :: "r"(s), "l"(gmem));
}
#define CP_COMMIT() asm volatile("cp.async.commit_group;\n" ::: "memory")
#define CP_WAIT(n)  asm volatile("cp.async.wait_group %0;\n" :: "n"(n) : "memory")

// raw fp32 bits fed to tf32 mma (HW truncates low mantissa bits)
__device__ __forceinline__ void mma8(float c[4], const uint32_t a[4], const uint32_t b[2]) {
    asm volatile(
        "mma.sync.aligned.m16n8k8.row.col.f32.tf32.tf32.f32 "
        "{%0,%1,%2,%3},{%4,%5,%6,%7},{%8,%9},{%0,%1,%2,%3};"
        : "+f"(c[0]), "+f"(c[1]), "+f"(c[2]), "+f"(c[3])
        : "r"(a[0]), "r"(a[1]), "r"(a[2]), "r"(a[3]), "r"(b[0]), "r"(b[1]));
}

// ============================================================================
// K1: fused QKV projection. out(192,4096) = Wqkv(192,512) @ X(512,4096) + bias
// grid (32 n-tiles, 16 batch), 384 threads (12 warps, 6x2), tile 192x128, BK=32
// ============================================================================
#define LDA1 36
#define LDB1 136
#define A1SZ (192 * LDA1)
#define B1SZ (32 * LDB1)

__global__ __launch_bounds__(384, 1) void qkv_kernel(
    const float* __restrict__ x,
    const float* __restrict__ wq, const float* __restrict__ bq,
    const float* __restrict__ wk, const float* __restrict__ bk,
    const float* __restrict__ wv, const float* __restrict__ bv)
{
    extern __shared__ float sm1[];
    float* As = sm1;              // [2][192][LDA1]
    float* Bs = sm1 + 2 * A1SZ;   // [2][32][LDB1]

    const int b = blockIdx.y;
    const int n0 = blockIdx.x * 128;
    const float* Xb = x + (size_t)b * CC * NN;

    const int tid = threadIdx.x;
    const int lane = tid & 31, warp = tid >> 5;
    const int wm = (warp % 6) * 32;        // m-offset in 192
    const int wn = (warp / 6) * 64;        // n-offset in 128
    const int gid = lane >> 2, tig = lane & 3;

    // per-thread load coords (A: 4 rows of f4; B: up to 3)
    int am[4], akv[4];
    const float* arow[4];
#pragma unroll
    for (int i = 0; i < 4; i++) {
        int v = tid + i * 384;
        am[i] = v >> 3; akv[i] = v & 7;
        int m = am[i];
        arow[i] = (m < 64 ? wq + (size_t)m * CC
                          : (m < 128 ? wk + (size_t)(m - 64) * CC
                                     : wv + (size_t)(m - 128) * CC)) + akv[i] * 4;
    }
    int bk_[3], bnv[3], bok[3];
#pragma unroll
    for (int i = 0; i < 3; i++) {
        int v = tid + i * 384;
        bok[i] = v < 1024;
        bk_[i] = v >> 5; bnv[i] = v & 31;
    }

    float acc[2][8][4];
#pragma unroll
    for (int i = 0; i < 2; i++)
#pragma unroll
        for (int j = 0; j < 8; j++)
#pragma unroll
            for (int q = 0; q < 4; q++) acc[i][j][q] = 0.f;

    // stage 0
    {
#pragma unroll
        for (int i = 0; i < 4; i++)
            cp_async16(As + am[i] * LDA1 + akv[i] * 4, arow[i]);
#pragma unroll
        for (int i = 0; i < 3; i++)
            if (bok[i])
                cp_async16(Bs + bk_[i] * LDB1 + bnv[i] * 4,
                           Xb + (size_t)bk_[i] * NN + n0 + bnv[i] * 4);
        CP_COMMIT();
    }

    for (int kt = 0; kt < 16; kt++) {
        const int buf = kt & 1;
        if (kt < 15) {
            const int k0 = (kt + 1) * 32;
            float* Ad = As + (buf ^ 1) * A1SZ;
            float* Bd = Bs + (buf ^ 1) * B1SZ;
#pragma unroll
            for (int i = 0; i < 4; i++)
                cp_async16(Ad + am[i] * LDA1 + akv[i] * 4, arow[i] + k0);
#pragma unroll
            for (int i = 0; i < 3; i++)
                if (bok[i])
                    cp_async16(Bd + bk_[i] * LDB1 + bnv[i] * 4,
                               Xb + (size_t)(k0 + bk_[i]) * NN + n0 + bnv[i] * 4);
            CP_COMMIT();
            CP_WAIT(1);
        } else {
            CP_WAIT(0);
        }
        __syncthreads();

        const uint32_t* Ab = reinterpret_cast<const uint32_t*>(As + buf * A1SZ);
        const uint32_t* Bb = reinterpret_cast<const uint32_t*>(Bs + buf * B1SZ);
#pragma unroll
        for (int kk = 0; kk < 4; kk++) {
            uint32_t af[2][4], bf[8][2];
#pragma unroll
            for (int mi = 0; mi < 2; mi++) {
                const uint32_t* ap = Ab + (wm + mi * 16 + gid) * LDA1 + kk * 8 + tig;
                af[mi][0] = ap[0];
                af[mi][1] = ap[8 * LDA1];
                af[mi][2] = ap[4];
                af[mi][3] = ap[8 * LDA1 + 4];
            }
#pragma unroll
            for (int ni = 0; ni < 8; ni++) {
                const uint32_t* bp = Bb + (kk * 8 + tig) * LDB1 + wn + ni * 8 + gid;
                bf[ni][0] = bp[0];
                bf[ni][1] = bp[4 * LDB1];
            }
#pragma unroll
            for (int mi = 0; mi < 2; mi++)
#pragma unroll
                for (int ni = 0; ni < 8; ni++) mma8(acc[mi][ni], af[mi], bf[ni]);
        }
        __syncthreads();
    }

    // epilogue: + bias, route to Q/K/V
    const int proj = wm >> 6;                       // 0,1,2
    float* out = proj == 0 ? g_Q : (proj == 1 ? g_K : g_V);
    const float* bias = proj == 0 ? bq : (proj == 1 ? bk : bv);
#pragma unroll
    for (int mi = 0; mi < 2; mi++) {
        int r0 = wm + mi * 16 + gid;
        int rl0 = r0 & 63, rl1 = (r0 + 8) & 63;
        float b0v = bias[rl0], b1v = bias[rl1];
#pragma unroll
        for (int ni = 0; ni < 8; ni++) {
            int cc = n0 + wn + ni * 8 + 2 * tig;
            *reinterpret_cast<float2*>(out + ((size_t)b * CPD + rl0) * NN + cc) =
                make_float2(acc[mi][ni][0] + b0v, acc[mi][ni][1] + b0v);
            *reinterpret_cast<float2*>(out + ((size_t)b * CPD + rl1) * NN + cc) =
                make_float2(acc[mi][ni][2] + b1v, acc[mi][ni][3] + b1v);
        }
    }
}

// ============================================================================
// K2: energy partials. E_part(64,64) = K[:, s*256:(s+1)*256] @ Q[...]^T
// grid (16 slices, 16 batch), 128 threads (4 warps, 2x2)
// ============================================================================
#define LDK2 36
#define LDQ2 40

__global__ __launch_bounds__(128) void energy_kernel()
{
    __shared__ float Ks[2][64][LDK2];
    __shared__ float Qs[2][64][LDQ2];
    const int s = blockIdx.x, b = blockIdx.y;
    const int nbase = s * 256;
    const float* Kb = g_K + (size_t)b * CPD * NN + nbase;
    const float* Qb = g_Q + (size_t)b * CPD * NN + nbase;

    const int tid = threadIdx.x, lane = tid & 31, warp = tid >> 5;
    const int wm = (warp & 1) * 32, wn = (warp >> 1) * 32;
    const int gid = lane >> 2, tig = lane & 3;

    int rr[4], rkv[4];
#pragma unroll
    for (int i = 0; i < 4; i++) {
        int v = tid + i * 128;
        rr[i] = v >> 3; rkv[i] = v & 7;
    }

    float acc[2][4][4];
#pragma unroll
    for (int i = 0; i < 2; i++)
#pragma unroll
        for (int j = 0; j < 4; j++)
#pragma unroll
            for (int q = 0; q < 4; q++) acc[i][j][q] = 0.f;

    // stage 0
#pragma unroll
    for (int i = 0; i < 4; i++) {
        cp_async16(&Ks[0][rr[i]][rkv[i] * 4], Kb + (size_t)rr[i] * NN + rkv[i] * 4);
        cp_async16(&Qs[0][rr[i]][rkv[i] * 4], Qb + (size_t)rr[i] * NN + rkv[i] * 4);
    }
    CP_COMMIT();

    for (int kt = 0; kt < 8; kt++) {
        const int buf = kt & 1;
        if (kt < 7) {
            const int k0 = (kt + 1) * 32;
#pragma unroll
            for (int i = 0; i < 4; i++) {
                cp_async16(&Ks[buf ^ 1][rr[i]][rkv[i] * 4],
                           Kb + (size_t)rr[i] * NN + k0 + rkv[i] * 4);
                cp_async16(&Qs[buf ^ 1][rr[i]][rkv[i] * 4],
                           Qb + (size_t)rr[i] * NN + k0 + rkv[i] * 4);
            }
            CP_COMMIT();
            CP_WAIT(1);
        } else {
            CP_WAIT(0);
        }
        __syncthreads();

#pragma unroll
        for (int kk = 0; kk < 4; kk++) {
            uint32_t af[2][4], bf[4][2];
#pragma unroll
            for (int mi = 0; mi < 2; mi++) {
                const uint32_t* ap =
                    reinterpret_cast<const uint32_t*>(&Ks[buf][wm + mi * 16 + gid][kk * 8 + tig]);
                af[mi][0] = ap[0];
                af[mi][1] = ap[8 * LDK2];
                af[mi][2] = ap[4];
                af[mi][3] = ap[8 * LDK2 + 4];
            }
#pragma unroll
            for (int ni = 0; ni < 4; ni++) {
                const uint32_t* bp =
                    reinterpret_cast<const uint32_t*>(&Qs[buf][wn + ni * 8 + gid][kk * 8 + tig]);
                bf[ni][0] = bp[0];
                bf[ni][1] = bp[4];
            }
#pragma unroll
            for (int mi = 0; mi < 2; mi++)
#pragma unroll
                for (int ni = 0; ni < 4; ni++) mma8(acc[mi][ni], af[mi], bf[ni]);
        }
        __syncthreads();
    }

    float* P = g_P + (size_t)(b * 16 + s) * CPD * CPD;
#pragma unroll
    for (int mi = 0; mi < 2; mi++) {
        int r0 = wm + mi * 16 + gid;
#pragma unroll
        for (int ni = 0; ni < 4; ni++) {
            int cc = wn + ni * 8 + 2 * tig;
            *reinterpret_cast<float2*>(P + (size_t)r0 * CPD + cc) =
                make_float2(acc[mi][ni][0], acc[mi][ni][1]);
            *reinterpret_cast<float2*>(P + (size_t)(r0 + 8) * CPD + cc) =
                make_float2(acc[mi][ni][2], acc[mi][ni][3]);
        }
    }
}

// ============================================================================
// K3: reduce partials + softmax + M = Wo @ A, fused. grid (16 b), 512 threads
// ============================================================================
__global__ __launch_bounds__(512) void softmax_momix_kernel(const float* __restrict__ wo)
{
    __shared__ float A[64][68];
    __shared__ float Wos[64][68];
    const int b = blockIdx.x, tid = threadIdx.x;

    for (int idx = tid; idx < 4096; idx += 512) {
        float ssum = 0.f;
#pragma unroll
        for (int p = 0; p < 16; p++)
            ssum += g_P[(size_t)(b * 16 + p) * 4096 + idx];
        A[idx >> 6][idx & 63] = ssum;
    }
    __syncthreads();
    if (tid < 64) {
        float m = -1e30f;
#pragma unroll
        for (int j = 0; j < 64; j++) m = fmaxf(m, A[tid][j]);
        float ssum = 0.f;
#pragma unroll
        for (int j = 0; j < 64; j++) {
            float e = __expf(A[tid][j] - m);
            A[tid][j] = e;
            ssum += e;
        }
        float inv = 1.f / ssum;
#pragma unroll
        for (int j = 0; j < 64; j++) A[tid][j] *= inv;
    }
    __syncthreads();

    // M = Wo @ A in 8 chunks of 64 c-rows
    const int cl = tid >> 3, jg = tid & 7;
    for (int ch = 0; ch < 8; ch++) {
        const int c0 = ch * 64;
#pragma unroll
        for (int i = 0; i < 2; i++) {
            int v = tid + i * 512, m = v >> 4, kv = v & 15;
            float4 t = *reinterpret_cast<const float4*>(wo + (size_t)(c0 + m) * CPD + kv * 4);
            *reinterpret_cast<float4*>(&Wos[m][kv * 4]) = t;
        }
        __syncthreads();

        float acc[8];
#pragma unroll
        for (int q = 0; q < 8; q++) acc[q] = 0.f;
#pragma unroll 8
        for (int o = 0; o < 64; o++) {
            float w = Wos[cl][o];
            const float4* ar = reinterpret_cast<const float4*>(&A[o][jg * 8]);
            float4 a0 = ar[0], a1 = ar[1];
            acc[0] += w * a0.x; acc[1] += w * a0.y; acc[2] += w * a0.z; acc[3] += w * a0.w;
            acc[4] += w * a1.x; acc[5] += w * a1.y; acc[6] += w * a1.z; acc[7] += w * a1.w;
        }
        float* dst = g_M + ((size_t)b * CC + c0 + cl) * CPD + jg * 8;
        *reinterpret_cast<float4*>(dst)     = make_float4(acc[0], acc[1], acc[2], acc[3]);
        *reinterpret_cast<float4*>(dst + 4) = make_float4(acc[4], acc[5], acc[6], acc[7]);
        __syncthreads();
    }
}

// ============================================================================
// K4: Y = gamma*(M @ V + bo) + X. tile 64(c) x 128(n), K=64 single stage
// grid (32 n-tiles, 8 c-tiles, 16 b), 256 threads (8 warps, 2x4)
// ============================================================================
#define LDM4 68
#define LDV4 136

__global__ __launch_bounds__(256, 2) void out_kernel(
    const float* __restrict__ x, const float* __restrict__ bo,
    const float* __restrict__ gamma, float* __restrict__ y)
{
    extern __shared__ float sm4[];
    float* Ms = sm4;               // [64][LDM4]
    float* Vs = sm4 + 64 * LDM4;   // [64][LDV4]

    const int n0 = blockIdx.x * 128, c0 = blockIdx.y * 64, b = blockIdx.z;
    const int tid = threadIdx.x, lane = tid & 31, warp = tid >> 5;
    const int wm = (warp & 1) * 32, wn = (warp >> 1) * 32;
    const int gid = lane >> 2, tig = lane & 3;

#pragma unroll
    for (int i = 0; i < 4; i++) {
        int v = tid + i * 256, m = v >> 4, kv = v & 15;
        *reinterpret_cast<float4*>(Ms + m * LDM4 + kv * 4) =
            *reinterpret_cast<const float4*>(g_M + ((size_t)b * CC + c0 + m) * CPD + kv * 4);
    }
#pragma unroll
    for (int i = 0; i < 8; i++) {
        int v = tid + i * 256, k = v >> 5, nv = v & 31;
        *reinterpret_cast<float4*>(Vs + k * LDV4 + nv * 4) =
            *reinterpret_cast<const float4*>(g_V + ((size_t)b * CPD + k) * NN + n0 + nv * 4);
    }
    __syncthreads();

    float acc[2][4][4];
#pragma unroll
    for (int i = 0; i < 2; i++)
#pragma unroll
        for (int j = 0; j < 4; j++)
#pragma unroll
            for (int q = 0; q < 4; q++) acc[i][j][q] = 0.f;

    const uint32_t* Mu = reinterpret_cast<const uint32_t*>(Ms);
    const uint32_t* Vu = reinterpret_cast<const uint32_t*>(Vs);
#pragma unroll
    for (int kk = 0; kk < 8; kk++) {
        uint32_t af[2][4], bf[4][2];
#pragma unroll
        for (int mi = 0; mi < 2; mi++) {
            const uint32_t* ap = Mu + (wm + mi * 16 + gid) * LDM4 + kk * 8 + tig;
            af[mi][0] = ap[0];
            af[mi][1] = ap[8 * LDM4];
            af[mi][2] = ap[4];
            af[mi][3] = ap[8 * LDM4 + 4];
        }
#pragma unroll
        for (int ni = 0; ni < 4; ni++) {
            const uint32_t* bp = Vu + (kk * 8 + tig) * LDV4 + wn + ni * 8 + gid;
            bf[ni][0] = bp[0];
            bf[ni][1] = bp[4 * LDV4];
        }
#pragma unroll
        for (int mi = 0; mi < 2; mi++)
#pragma unroll
            for (int ni = 0; ni < 4; ni++) mma8(acc[mi][ni], af[mi], bf[ni]);
    }

    const float g = gamma[0];
#pragma unroll
    for (int mi = 0; mi < 2; mi++) {
        int r0 = wm + mi * 16 + gid;
        int ch0 = c0 + r0, ch1 = c0 + r0 + 8;
        float bo0 = bo[ch0], bo1 = bo[ch1];
#pragma unroll
        for (int ni = 0; ni < 4; ni++) {
            int nn = n0 + wn + ni * 8 + 2 * tig;
            size_t off0 = ((size_t)b * CC + ch0) * NN + nn;
            size_t off1 = ((size_t)b * CC + ch1) * NN + nn;
            float2 x0 = *reinterpret_cast<const float2*>(x + off0);
            float2 x1 = *reinterpret_cast<const float2*>(x + off1);
            float2 o0, o1;
            o0.x = g * (acc[mi][ni][0] + bo0) + x0.x;
            o0.y = g * (acc[mi][ni][1] + bo0) + x0.y;
            o1.x = g * (acc[mi][ni][2] + bo1) + x1.x;
            o1.y = g * (acc[mi][ni][3] + bo1) + x1.y;
            *reinterpret_cast<float2*>(y + off0) = o0;
            *reinterpret_cast<float2*>(y + off1) = o1;
        }
    }
}

// ============================================================================
extern "C" void kernel_launch(void* const* d_in, const int* in_sizes, int n_in,
                              void* d_out, int out_size)
{
    const float* x  = (const float*)d_in[0];
    const float* wq = (const float*)d_in[1];
    const float* bq = (const float*)d_in[2];
    const float* wk = (const float*)d_in[3];
    const float* bk = (const float*)d_in[4];
    const float* wv = (const float*)d_in[5];
    const float* bv = (const float*)d_in[6];
    const float* wo = (const float*)d_in[7];
    const float* bo = (const float*)d_in[8];
    const float* gm = (const float*)d_in[9];
    float* y = (float*)d_out;

    static int inited = 0;
    if (!inited) {
        cudaFuncSetAttribute(qkv_kernel, cudaFuncAttributeMaxDynamicSharedMemorySize,
                             (2 * A1SZ + 2 * B1SZ) * 4);
        cudaFuncSetAttribute(out_kernel, cudaFuncAttributeMaxDynamicSharedMemorySize,
                             (64 * LDM4 + 64 * LDV4) * 4);
        inited = 1;
    }

    qkv_kernel<<<dim3(32, 16), 384, (2 * A1SZ + 2 * B1SZ) * 4>>>(x, wq, bq, wk, bk, wv, bv);
    energy_kernel<<<dim3(16, 16), 128>>>();
    softmax_momix_kernel<<<16, 512>>>(wo);
    out_kernel<<<dim3(32, 8, 16), 256, (64 * LDM4 + 64 * LDV4) * 4>>>(x, bo, gm, y);
}

// round 4
// speedup vs baseline: 1.4682x; 1.4682x over previous
#include <cuda_runtime.h>
#include <cuda_fp16.h>
#include <cstdint>

#define NB 16
#define CC 512
#define CPD 64
#define NN 4096

// scratch (static __device__ — no allocation)
__device__ __half g_Q[(size_t)NB * CPD * NN];
__device__ __half g_K[(size_t)NB * CPD * NN];
__device__ __half g_V[(size_t)NB * CPD * NN];
__device__ float  g_P[(size_t)NB * 16 * CPD * CPD]; // energy partials (fp32)
__device__ __half g_M[NB * CC * CPD];               // M = Wo @ A (fp16)

__device__ __forceinline__ void cp_async16(void* smem, const void* gmem) {
    uint32_t s = (uint32_t)__cvta_generic_to_shared(smem);
    asm volatile("cp.async.cg.shared.global [%0], [%1], 16;\n" :: "r"(s), "l"(gmem));
}
#define CP_COMMIT() asm volatile("cp.async.commit_group;\n" ::: "memory")
#define CP_WAIT(n)  asm volatile("cp.async.wait_group %0;\n" :: "n"(n) : "memory")

// fp16 mma: D(f32) += A(f16,row) * B(f16,col), m16n8k16
__device__ __forceinline__ void mma16(float c[4], const uint32_t a[4], const uint32_t b[2]) {
    asm volatile(
        "mma.sync.aligned.m16n8k16.row.col.f32.f16.f16.f32 "
        "{%0,%1,%2,%3},{%4,%5,%6,%7},{%8,%9},{%0,%1,%2,%3};"
        : "+f"(c[0]), "+f"(c[1]), "+f"(c[2]), "+f"(c[3])
        : "r"(a[0]), "r"(a[1]), "r"(a[2]), "r"(a[3]), "r"(b[0]), "r"(b[1]));
}

__device__ __forceinline__ void sth2(__half* p, float a, float b) {
    *reinterpret_cast<__half2*>(p) = __floats2half2_rn(a, b);
}

// ============================================================================
// K1: fused QKV. out(192,4096) = Wqkv(192,512) @ X(512,4096) + bias  [fp16 mma]
// grid (32 n-tiles, 16 b), 384 threads (12 warps: 6m x 2n), tile 192x128, BK=32
// smem (halves): A[2][192][40] @0/7680, B[2][128][40] @15360/20480
// ============================================================================
#define A0H 0
#define A1H 7680
#define B0H 15360
#define B1H 20480
#define K1_SMEMB 51200

__global__ __launch_bounds__(384, 1) void qkv_kernel(
    const float* __restrict__ x,
    const float* __restrict__ wq, const float* __restrict__ bq,
    const float* __restrict__ wk, const float* __restrict__ bk,
    const float* __restrict__ wv, const float* __restrict__ bv)
{
    extern __shared__ __half smh[];
    const int b = blockIdx.y;
    const int n0 = blockIdx.x * 128;
    const float* Xb = x + (size_t)b * CC * NN;

    const int tid = threadIdx.x;
    const int lane = tid & 31, warp = tid >> 5;
    const int wm = (warp % 6) * 32;      // m-offset in 192
    const int wn = (warp / 6) * 64;      // n-offset in 128
    const int gid = lane >> 2, tig = lane & 3;

    // A (weights) coords: 1536 float4/stage, 4 per thread
    const float* asrc[4];
    int aoff[4];
#pragma unroll
    for (int i = 0; i < 4; i++) {
        int v = tid + i * 384;
        int r = v >> 3, kv = v & 7;
        const float* wr = r < 64 ? wq + (size_t)r * CC
                        : r < 128 ? wk + (size_t)(r - 64) * CC
                                  : wv + (size_t)(r - 128) * CC;
        asrc[i] = wr + kv * 4;
        aoff[i] = r * 40 + kv * 4;       // halves
    }
    // B (X transpose) coords: 2048 k-pairs/stage; 5 full + 1 predicated
    int bn[6], bkp[6];
#pragma unroll
    for (int i = 0; i < 6; i++) {
        int v = tid + i * 384;
        bn[i] = v & 127; bkp[i] = v >> 7;
    }
    const bool b5 = (tid < 128);

    float acc[2][8][4];
#pragma unroll
    for (int i = 0; i < 2; i++)
#pragma unroll
        for (int j = 0; j < 8; j++)
#pragma unroll
            for (int q = 0; q < 4; q++) acc[i][j][q] = 0.f;

    float4 pa[4];
    float2 pb[6];

    // prologue: k-tile 0 -> buf0
#pragma unroll
    for (int i = 0; i < 4; i++) pa[i] = *reinterpret_cast<const float4*>(asrc[i]);
#pragma unroll
    for (int i = 0; i < 5; i++) {
        pb[i].x = Xb[(size_t)(2 * bkp[i]) * NN + n0 + bn[i]];
        pb[i].y = Xb[(size_t)(2 * bkp[i] + 1) * NN + n0 + bn[i]];
    }
    if (b5) {
        pb[5].x = Xb[(size_t)(2 * bkp[5]) * NN + n0 + bn[5]];
        pb[5].y = Xb[(size_t)(2 * bkp[5] + 1) * NN + n0 + bn[5]];
    }
    {
        __half* Ad = smh + A0H;
        __half* Bd = smh + B0H;
#pragma unroll
        for (int i = 0; i < 4; i++) {
            sth2(Ad + aoff[i],     pa[i].x, pa[i].y);
            sth2(Ad + aoff[i] + 2, pa[i].z, pa[i].w);
        }
#pragma unroll
        for (int i = 0; i < 5; i++) sth2(Bd + bn[i] * 40 + 2 * bkp[i], pb[i].x, pb[i].y);
        if (b5) sth2(Bd + bn[5] * 40 + 2 * bkp[5], pb[5].x, pb[5].y);
    }
    __syncthreads();

    for (int kt = 0; kt < 16; kt++) {
        const int buf = kt & 1;
        if (kt < 15) {
            const int k0 = (kt + 1) * 32;
#pragma unroll
            for (int i = 0; i < 4; i++) pa[i] = *reinterpret_cast<const float4*>(asrc[i] + k0);
#pragma unroll
            for (int i = 0; i < 5; i++) {
                pb[i].x = Xb[(size_t)(k0 + 2 * bkp[i]) * NN + n0 + bn[i]];
                pb[i].y = Xb[(size_t)(k0 + 2 * bkp[i] + 1) * NN + n0 + bn[i]];
            }
            if (b5) {
                pb[5].x = Xb[(size_t)(k0 + 2 * bkp[5]) * NN + n0 + bn[5]];
                pb[5].y = Xb[(size_t)(k0 + 2 * bkp[5] + 1) * NN + n0 + bn[5]];
            }
        }

        const uint32_t* A32 = reinterpret_cast<const uint32_t*>(smh + (buf ? A1H : A0H));
        const uint32_t* B32 = reinterpret_cast<const uint32_t*>(smh + (buf ? B1H : B0H));
#pragma unroll
        for (int kk = 0; kk < 2; kk++) {
            uint32_t af[2][4], bf[8][2];
#pragma unroll
            for (int mi = 0; mi < 2; mi++) {
                int base = (wm + mi * 16 + gid) * 20 + kk * 8 + tig;
                af[mi][0] = A32[base];
                af[mi][1] = A32[base + 8 * 20];
                af[mi][2] = A32[base + 4];
                af[mi][3] = A32[base + 8 * 20 + 4];
            }
#pragma unroll
            for (int ni = 0; ni < 8; ni++) {
                int base = (wn + ni * 8 + gid) * 20 + kk * 8 + tig;
                bf[ni][0] = B32[base];
                bf[ni][1] = B32[base + 4];
            }
#pragma unroll
            for (int mi = 0; mi < 2; mi++)
#pragma unroll
                for (int ni = 0; ni < 8; ni++) mma16(acc[mi][ni], af[mi], bf[ni]);
        }

        if (kt < 15) {
            __half* Ad = smh + (buf ? A0H : A1H);
            __half* Bd = smh + (buf ? B0H : B1H);
#pragma unroll
            for (int i = 0; i < 4; i++) {
                sth2(Ad + aoff[i],     pa[i].x, pa[i].y);
                sth2(Ad + aoff[i] + 2, pa[i].z, pa[i].w);
            }
#pragma unroll
            for (int i = 0; i < 5; i++) sth2(Bd + bn[i] * 40 + 2 * bkp[i], pb[i].x, pb[i].y);
            if (b5) sth2(Bd + bn[5] * 40 + 2 * bkp[5], pb[5].x, pb[5].y);
            __syncthreads();
        }
    }
    __syncthreads();

    // epilogue: 3 passes via smem staging buf [64][136] halves
    __half* buf = smh;
    const int pw = (warp % 6) >> 1;      // this warp's projection
    const int wml = ((warp % 6) & 1) * 32;
#pragma unroll
    for (int p = 0; p < 3; p++) {
        if (pw == p) {
            const float* bias = p == 0 ? bq : (p == 1 ? bk : bv);
#pragma unroll
            for (int mi = 0; mi < 2; mi++) {
                int rl = wml + mi * 16 + gid;
                float b0v = bias[rl], b1v = bias[rl + 8];
#pragma unroll
                for (int ni = 0; ni < 8; ni++) {
                    int col = wn + ni * 8 + 2 * tig;
                    sth2(buf + rl * 136 + col,       acc[mi][ni][0] + b0v, acc[mi][ni][1] + b0v);
                    sth2(buf + (rl + 8) * 136 + col, acc[mi][ni][2] + b1v, acc[mi][ni][3] + b1v);
                }
            }
        }
        __syncthreads();
        __half* gp = p == 0 ? g_Q : (p == 1 ? g_K : g_V);
#pragma unroll
        for (int i = 0; i < 3; i++) {
            int v = tid + i * 384;
            if (v < 1024) {
                int row = v >> 4, c = v & 15;
                uint4 t = *reinterpret_cast<const uint4*>(buf + row * 136 + c * 8);
                *reinterpret_cast<uint4*>(gp + ((size_t)b * CPD + row) * NN + n0 + c * 8) = t;
            }
        }
        __syncthreads();
    }
}

// ============================================================================
// K2: energy partials. E_part(64,64) = K_slice(64,256) @ Q_slice^T  [fp16 mma]
// grid (16 slices, 16 b), 128 threads (4 warps, 2x2)
// ============================================================================
__global__ __launch_bounds__(128) void energy_kernel()
{
    __shared__ __half Ks[2][64][40];
    __shared__ __half Qs[2][64][40];
    const int s = blockIdx.x, b = blockIdx.y;
    const int nbase = s * 256;
    const __half* Kb = g_K + (size_t)b * CPD * NN + nbase;
    const __half* Qb = g_Q + (size_t)b * CPD * NN + nbase;

    const int tid = threadIdx.x, lane = tid & 31, warp = tid >> 5;
    const int wm = (warp & 1) * 32, wn = (warp >> 1) * 32;
    const int gid = lane >> 2, tig = lane & 3;

    int rr[2], rsg[2];
#pragma unroll
    for (int i = 0; i < 2; i++) {
        int v = tid + i * 128;
        rr[i] = v >> 2; rsg[i] = v & 3;
    }

    float acc[2][4][4];
#pragma unroll
    for (int i = 0; i < 2; i++)
#pragma unroll
        for (int j = 0; j < 4; j++)
#pragma unroll
            for (int q = 0; q < 4; q++) acc[i][j][q] = 0.f;

#pragma unroll
    for (int i = 0; i < 2; i++) {
        cp_async16(&Ks[0][rr[i]][rsg[i] * 8], Kb + (size_t)rr[i] * NN + rsg[i] * 8);
        cp_async16(&Qs[0][rr[i]][rsg[i] * 8], Qb + (size_t)rr[i] * NN + rsg[i] * 8);
    }
    CP_COMMIT();

    for (int kt = 0; kt < 8; kt++) {
        const int buf = kt & 1;
        if (kt < 7) {
            const int k0 = (kt + 1) * 32;
#pragma unroll
            for (int i = 0; i < 2; i++) {
                cp_async16(&Ks[buf ^ 1][rr[i]][rsg[i] * 8],
                           Kb + (size_t)rr[i] * NN + k0 + rsg[i] * 8);
                cp_async16(&Qs[buf ^ 1][rr[i]][rsg[i] * 8],
                           Qb + (size_t)rr[i] * NN + k0 + rsg[i] * 8);
            }
            CP_COMMIT();
            CP_WAIT(1);
        } else {
            CP_WAIT(0);
        }
        __syncthreads();

        const uint32_t* A32 = reinterpret_cast<const uint32_t*>(&Ks[buf][0][0]);
        const uint32_t* B32 = reinterpret_cast<const uint32_t*>(&Qs[buf][0][0]);
#pragma unroll
        for (int kk = 0; kk < 2; kk++) {
            uint32_t af[2][4], bf[4][2];
#pragma unroll
            for (int mi = 0; mi < 2; mi++) {
                int base = (wm + mi * 16 + gid) * 20 + kk * 8 + tig;
                af[mi][0] = A32[base];
                af[mi][1] = A32[base + 160];
                af[mi][2] = A32[base + 4];
                af[mi][3] = A32[base + 164];
            }
#pragma unroll
            for (int ni = 0; ni < 4; ni++) {
                int base = (wn + ni * 8 + gid) * 20 + kk * 8 + tig;
                bf[ni][0] = B32[base];
                bf[ni][1] = B32[base + 4];
            }
#pragma unroll
            for (int mi = 0; mi < 2; mi++)
#pragma unroll
                for (int ni = 0; ni < 4; ni++) mma16(acc[mi][ni], af[mi], bf[ni]);
        }
        __syncthreads();
    }

    float* P = g_P + (size_t)(b * 16 + s) * CPD * CPD;
#pragma unroll
    for (int mi = 0; mi < 2; mi++) {
        int r0 = wm + mi * 16 + gid;
#pragma unroll
        for (int ni = 0; ni < 4; ni++) {
            int cc = wn + ni * 8 + 2 * tig;
            *reinterpret_cast<float2*>(P + (size_t)r0 * CPD + cc) =
                make_float2(acc[mi][ni][0], acc[mi][ni][1]);
            *reinterpret_cast<float2*>(P + (size_t)(r0 + 8) * CPD + cc) =
                make_float2(acc[mi][ni][2], acc[mi][ni][3]);
        }
    }
}

// ============================================================================
// K3: reduce + softmax + M = Wo @ A (fp32 compute, fp16 store)
// grid (4 cgroups, 16 b), 512 threads
// ============================================================================
__global__ __launch_bounds__(512) void softmax_momix_kernel(const float* __restrict__ wo)
{
    __shared__ float A[64][68];
    __shared__ float Wos[64][68];
    const int cg = blockIdx.x, b = blockIdx.y, tid = threadIdx.x;

    for (int idx = tid; idx < 4096; idx += 512) {
        float ssum = 0.f;
#pragma unroll
        for (int p = 0; p < 16; p++)
            ssum += g_P[(size_t)(b * 16 + p) * 4096 + idx];
        A[idx >> 6][idx & 63] = ssum;
    }
    __syncthreads();
    if (tid < 64) {
        float m = -1e30f;
#pragma unroll
        for (int j = 0; j < 64; j++) m = fmaxf(m, A[tid][j]);
        float ssum = 0.f;
#pragma unroll
        for (int j = 0; j < 64; j++) {
            float e = __expf(A[tid][j] - m);
            A[tid][j] = e;
            ssum += e;
        }
        float inv = 1.f / ssum;
#pragma unroll
        for (int j = 0; j < 64; j++) A[tid][j] *= inv;
    }
    __syncthreads();

    const int cl = tid >> 3, jg = tid & 7;
    for (int ci = 0; ci < 2; ci++) {
        const int c0 = (cg * 2 + ci) * 64;
#pragma unroll
        for (int i = 0; i < 2; i++) {
            int v = tid + i * 512, m = v >> 4, kv = v & 15;
            *reinterpret_cast<float4*>(&Wos[m][kv * 4]) =
                *reinterpret_cast<const float4*>(wo + (size_t)(c0 + m) * CPD + kv * 4);
        }
        __syncthreads();

        float acc[8];
#pragma unroll
        for (int q = 0; q < 8; q++) acc[q] = 0.f;
#pragma unroll 8
        for (int o = 0; o < 64; o++) {
            float w = Wos[cl][o];
            const float4* ar = reinterpret_cast<const float4*>(&A[o][jg * 8]);
            float4 a0 = ar[0], a1 = ar[1];
            acc[0] += w * a0.x; acc[1] += w * a0.y; acc[2] += w * a0.z; acc[3] += w * a0.w;
            acc[4] += w * a1.x; acc[5] += w * a1.y; acc[6] += w * a1.z; acc[7] += w * a1.w;
        }
        __half2 h0 = __floats2half2_rn(acc[0], acc[1]);
        __half2 h1 = __floats2half2_rn(acc[2], acc[3]);
        __half2 h2 = __floats2half2_rn(acc[4], acc[5]);
        __half2 h3 = __floats2half2_rn(acc[6], acc[7]);
        uint4 u;
        u.x = *reinterpret_cast<uint32_t*>(&h0);
        u.y = *reinterpret_cast<uint32_t*>(&h1);
        u.z = *reinterpret_cast<uint32_t*>(&h2);
        u.w = *reinterpret_cast<uint32_t*>(&h3);
        *reinterpret_cast<uint4*>(g_M + ((size_t)b * CC + c0 + cl) * CPD + jg * 8) = u;
        __syncthreads();
    }
}

// ============================================================================
// K4: Y = gamma*(M @ V + bo) + X.  [fp16 mma]
// grid (32 n-tiles, 16 b), 256 threads (8 warps: 2m x 4n).
// V tile transposed once to Vt[128][72]; M chunks double-buffered Ms[2][64][72].
// smem halves: Vt @0 (9216), Ms @9216 (9216), Vraw overlays @13824 (8704)
// ============================================================================
__global__ __launch_bounds__(256) void out_kernel(
    const float* __restrict__ x, const float* __restrict__ bo,
    const float* __restrict__ gamma, float* __restrict__ y)
{
    __shared__ __half sm4[22528];
    __half* Vt = sm4;                 // [128][72]
    __half* Ms = sm4 + 9216;          // [2][64][72]
    __half* Vraw = sm4 + 13824;       // [64][136] (overlays Ms[1] pre-loop)

    const int n0 = blockIdx.x * 128, b = blockIdx.y;
    const int tid = threadIdx.x, lane = tid & 31, warp = tid >> 5;
    const int wm = (warp & 1) * 32, wn = (warp >> 1) * 32;
    const int gid = lane >> 2, tig = lane & 3;

    // group0: Vraw + M0
#pragma unroll
    for (int i = 0; i < 4; i++) {
        int v = tid + i * 256, r = v >> 4, sg = v & 15;
        cp_async16(Vraw + r * 136 + sg * 8,
                   g_V + ((size_t)b * CPD + r) * NN + n0 + sg * 8);
    }
#pragma unroll
    for (int i = 0; i < 2; i++) {
        int v = tid + i * 256, r = v >> 3, sg = v & 7;
        cp_async16(Ms + r * 72 + sg * 8,
                   g_M + ((size_t)b * CC + r) * CPD + sg * 8);
    }
    CP_COMMIT();
    CP_WAIT(0);
    __syncthreads();

    // transpose Vraw[cp][n] -> Vt[n][cp]
    {
        const int n = tid & 127, cph = tid >> 7;
#pragma unroll
        for (int j = 0; j < 16; j++) {
            int cp = 2 * cph + 4 * j;
            __half a = Vraw[cp * 136 + n];
            __half c = Vraw[(cp + 1) * 136 + n];
            *reinterpret_cast<__half2*>(Vt + n * 72 + cp) = __halves2half2(a, c);
        }
    }
    __syncthreads();

    const float g = gamma[0];

    for (int ch = 0; ch < 8; ch++) {
        const int buf = ch & 1;
        const int c0 = ch * 64;
        if (ch < 7) {
            __half* Md = Ms + (buf ^ 1) * 4608;
#pragma unroll
            for (int i = 0; i < 2; i++) {
                int v = tid + i * 256, r = v >> 3, sg = v & 7;
                cp_async16(Md + r * 72 + sg * 8,
                           g_M + ((size_t)b * CC + c0 + 64 + r) * CPD + sg * 8);
            }
            CP_COMMIT();
            CP_WAIT(1);
        } else {
            CP_WAIT(0);
        }
        __syncthreads();

        float acc[2][4][4];
#pragma unroll
        for (int i = 0; i < 2; i++)
#pragma unroll
            for (int j = 0; j < 4; j++)
#pragma unroll
                for (int q = 0; q < 4; q++) acc[i][j][q] = 0.f;

        const uint32_t* A32 = reinterpret_cast<const uint32_t*>(Ms + buf * 4608);
        const uint32_t* B32 = reinterpret_cast<const uint32_t*>(Vt);
#pragma unroll
        for (int kk = 0; kk < 4; kk++) {
            uint32_t af[2][4], bf[4][2];
#pragma unroll
            for (int mi = 0; mi < 2; mi++) {
                int base = (wm + mi * 16 + gid) * 36 + kk * 8 + tig;
                af[mi][0] = A32[base];
                af[mi][1] = A32[base + 8 * 36];
                af[mi][2] = A32[base + 4];
                af[mi][3] = A32[base + 8 * 36 + 4];
            }
#pragma unroll
            for (int ni = 0; ni < 4; ni++) {
                int base = (wn + ni * 8 + gid) * 36 + kk * 8 + tig;
                bf[ni][0] = B32[base];
                bf[ni][1] = B32[base + 4];
            }
#pragma unroll
            for (int mi = 0; mi < 2; mi++)
#pragma unroll
                for (int ni = 0; ni < 4; ni++) mma16(acc[mi][ni], af[mi], bf[ni]);
        }

#pragma unroll
        for (int mi = 0; mi < 2; mi++) {
            int r0 = wm + mi * 16 + gid;
            int ch0 = c0 + r0, ch1 = c0 + r0 + 8;
            float bo0 = bo[ch0], bo1 = bo[ch1];
#pragma unroll
            for (int ni = 0; ni < 4; ni++) {
                int nn = n0 + wn + ni * 8 + 2 * tig;
                size_t off0 = ((size_t)b * CC + ch0) * NN + nn;
                size_t off1 = ((size_t)b * CC + ch1) * NN + nn;
                float2 x0 = *reinterpret_cast<const float2*>(x + off0);
                float2 x1 = *reinterpret_cast<const float2*>(x + off1);
                float2 o0, o1;
                o0.x = g * (acc[mi][ni][0] + bo0) + x0.x;
                o0.y = g * (acc[mi][ni][1] + bo0) + x0.y;
                o1.x = g * (acc[mi][ni][2] + bo1) + x1.x;
                o1.y = g * (acc[mi][ni][3] + bo1) + x1.y;
                *reinterpret_cast<float2*>(y + off0) = o0;
                *reinterpret_cast<float2*>(y + off1) = o1;
            }
        }
        __syncthreads();
    }
}

// ============================================================================
extern "C" void kernel_launch(void* const* d_in, const int* in_sizes, int n_in,
                              void* d_out, int out_size)
{
    const float* x  = (const float*)d_in[0];
    const float* wq = (const float*)d_in[1];
    const float* bq = (const float*)d_in[2];
    const float* wk = (const float*)d_in[3];
    const float* bk = (const float*)d_in[4];
    const float* wv = (const float*)d_in[5];
    const float* bv = (const float*)d_in[6];
    const float* wo = (const float*)d_in[7];
    const float* bo = (const float*)d_in[8];
    const float* gm = (const float*)d_in[9];
    float* y = (float*)d_out;

    static int inited = 0;
    if (!inited) {
        cudaFuncSetAttribute(qkv_kernel, cudaFuncAttributeMaxDynamicSharedMemorySize, K1_SMEMB);
        inited = 1;
    }

    qkv_kernel<<<dim3(32, 16), 384, K1_SMEMB>>>(x, wq, bq, wk, bk, wv, bv);
    energy_kernel<<<dim3(16, 16), 128>>>();
    softmax_momix_kernel<<<dim3(4, 16), 512>>>(wo);
    out_kernel<<<dim3(32, 16), 256>>>(x, bo, gm, y);
}

// round 5
// speedup vs baseline: 1.4787x; 1.0071x over previous
#include <cuda_runtime.h>
#include <cuda_fp16.h>
#include <cstdint>

#define NB 16
#define CC 512
#define CPD 64
#define NN 4096

// scratch (static __device__ — no allocation)
__device__ __half g_V[(size_t)NB * CPD * NN];
__device__ float  g_P[(size_t)NB * 32 * CPD * CPD]; // energy partials (32 n-slices)
__device__ __half g_M[NB * CC * CPD];               // M = Wo @ A (fp16)

__device__ __forceinline__ void cp_async16(void* smem, const void* gmem) {
    uint32_t s = (uint32_t)__cvta_generic_to_shared(smem);
    asm volatile("cp.async.cg.shared.global [%0], [%1], 16;\n" :: "r"(s), "l"(gmem));
}
#define CP_COMMIT() asm volatile("cp.async.commit_group;\n" ::: "memory")
#define CP_WAIT(n)  asm volatile("cp.async.wait_group %0;\n" :: "n"(n) : "memory")

// fp16 mma: D(f32) += A(f16,row) * B(f16,col), m16n8k16
__device__ __forceinline__ void mma16(float c[4], const uint32_t a[4], const uint32_t b[2]) {
    asm volatile(
        "mma.sync.aligned.m16n8k16.row.col.f32.f16.f16.f32 "
        "{%0,%1,%2,%3},{%4,%5,%6,%7},{%8,%9},{%0,%1,%2,%3};"
        : "+f"(c[0]), "+f"(c[1]), "+f"(c[2]), "+f"(c[3])
        : "r"(a[0]), "r"(a[1]), "r"(a[2]), "r"(a[3]), "r"(b[0]), "r"(b[1]));
}

__device__ __forceinline__ void sth2(__half* p, float a, float b) {
    *reinterpret_cast<__half2*>(p) = __floats2half2_rn(a, b);
}

// ============================================================================
// K1: fused QKV projection + energy partial.
//   QKV(192,128) = Wqkv(192,512) @ X_tile(512,128) + bias   [fp16 mma]
//   E_part(64,64) = K_tile(64,128) @ Q_tile(64,128)^T  -> g_P[b*32 + ntile]
//   V_tile -> g_V.  Q,K never touch HBM.
// grid (32 n-tiles, 16 b), 384 threads (12 warps: 6m x 2n), BK=32
// smem (halves): A[2][192][40] @0/7680, B[2][128][40] @15360/20480
// epilogue reuse: bufQ @0 [64][136], bufK @8704 [64][136]
// ============================================================================
#define A0H 0
#define A1H 7680
#define B0H 15360
#define B1H 20480
#define K1_SMEMB 51200

__global__ __launch_bounds__(384, 1) void qkv_energy_kernel(
    const float* __restrict__ x,
    const float* __restrict__ wq, const float* __restrict__ bq,
    const float* __restrict__ wk, const float* __restrict__ bk,
    const float* __restrict__ wv, const float* __restrict__ bv)
{
    extern __shared__ __half smh[];
    const int b = blockIdx.y;
    const int n0 = blockIdx.x * 128;
    const float* Xb = x + (size_t)b * CC * NN;

    const int tid = threadIdx.x;
    const int lane = tid & 31, warp = tid >> 5;
    const int wm = (warp % 6) * 32;      // m-offset in 192
    const int wn = (warp / 6) * 64;      // n-offset in 128
    const int gid = lane >> 2, tig = lane & 3;

    // A (weights) coords: 1536 float4/stage, 4 per thread
    const float* asrc[4];
    int aoff[4];
#pragma unroll
    for (int i = 0; i < 4; i++) {
        int v = tid + i * 384;
        int r = v >> 3, kv = v & 7;
        const float* wr = r < 64 ? wq + (size_t)r * CC
                        : r < 128 ? wk + (size_t)(r - 64) * CC
                                  : wv + (size_t)(r - 128) * CC;
        asrc[i] = wr + kv * 4;
        aoff[i] = r * 40 + kv * 4;       // halves
    }
    // B (X transpose) coords: 2048 k-pairs/stage; 5 full + 1 predicated
    int bn[6], bkp[6];
#pragma unroll
    for (int i = 0; i < 6; i++) {
        int v = tid + i * 384;
        bn[i] = v & 127; bkp[i] = v >> 7;
    }
    const bool b5 = (tid < 128);

    float acc[2][8][4];
#pragma unroll
    for (int i = 0; i < 2; i++)
#pragma unroll
        for (int j = 0; j < 8; j++)
#pragma unroll
            for (int q = 0; q < 4; q++) acc[i][j][q] = 0.f;

    float4 pa[4];
    float2 pb[6];

    // prologue: k-tile 0 -> buf0
#pragma unroll
    for (int i = 0; i < 4; i++) pa[i] = *reinterpret_cast<const float4*>(asrc[i]);
#pragma unroll
    for (int i = 0; i < 5; i++) {
        pb[i].x = Xb[(size_t)(2 * bkp[i]) * NN + n0 + bn[i]];
        pb[i].y = Xb[(size_t)(2 * bkp[i] + 1) * NN + n0 + bn[i]];
    }
    if (b5) {
        pb[5].x = Xb[(size_t)(2 * bkp[5]) * NN + n0 + bn[5]];
        pb[5].y = Xb[(size_t)(2 * bkp[5] + 1) * NN + n0 + bn[5]];
    }
    {
        __half* Ad = smh + A0H;
        __half* Bd = smh + B0H;
#pragma unroll
        for (int i = 0; i < 4; i++) {
            sth2(Ad + aoff[i],     pa[i].x, pa[i].y);
            sth2(Ad + aoff[i] + 2, pa[i].z, pa[i].w);
        }
#pragma unroll
        for (int i = 0; i < 5; i++) sth2(Bd + bn[i] * 40 + 2 * bkp[i], pb[i].x, pb[i].y);
        if (b5) sth2(Bd + bn[5] * 40 + 2 * bkp[5], pb[5].x, pb[5].y);
    }
    __syncthreads();

    for (int kt = 0; kt < 16; kt++) {
        const int buf = kt & 1;
        if (kt < 15) {
            const int k0 = (kt + 1) * 32;
#pragma unroll
            for (int i = 0; i < 4; i++) pa[i] = *reinterpret_cast<const float4*>(asrc[i] + k0);
#pragma unroll
            for (int i = 0; i < 5; i++) {
                pb[i].x = Xb[(size_t)(k0 + 2 * bkp[i]) * NN + n0 + bn[i]];
                pb[i].y = Xb[(size_t)(k0 + 2 * bkp[i] + 1) * NN + n0 + bn[i]];
            }
            if (b5) {
                pb[5].x = Xb[(size_t)(k0 + 2 * bkp[5]) * NN + n0 + bn[5]];
                pb[5].y = Xb[(size_t)(k0 + 2 * bkp[5] + 1) * NN + n0 + bn[5]];
            }
        }

        const uint32_t* A32 = reinterpret_cast<const uint32_t*>(smh + (buf ? A1H : A0H));
        const uint32_t* B32 = reinterpret_cast<const uint32_t*>(smh + (buf ? B1H : B0H));
#pragma unroll
        for (int kk = 0; kk < 2; kk++) {
            uint32_t af[2][4], bf[8][2];
#pragma unroll
            for (int mi = 0; mi < 2; mi++) {
                int base = (wm + mi * 16 + gid) * 20 + kk * 8 + tig;
                af[mi][0] = A32[base];
                af[mi][1] = A32[base + 8 * 20];
                af[mi][2] = A32[base + 4];
                af[mi][3] = A32[base + 8 * 20 + 4];
            }
#pragma unroll
            for (int ni = 0; ni < 8; ni++) {
                int base = (wn + ni * 8 + gid) * 20 + kk * 8 + tig;
                bf[ni][0] = B32[base];
                bf[ni][1] = B32[base + 4];
            }
#pragma unroll
            for (int mi = 0; mi < 2; mi++)
#pragma unroll
                for (int ni = 0; ni < 8; ni++) mma16(acc[mi][ni], af[mi], bf[ni]);
        }

        if (kt < 15) {
            __half* Ad = smh + (buf ? A0H : A1H);
            __half* Bd = smh + (buf ? B0H : B1H);
#pragma unroll
            for (int i = 0; i < 4; i++) {
                sth2(Ad + aoff[i],     pa[i].x, pa[i].y);
                sth2(Ad + aoff[i] + 2, pa[i].z, pa[i].w);
            }
#pragma unroll
            for (int i = 0; i < 5; i++) sth2(Bd + bn[i] * 40 + 2 * bkp[i], pb[i].x, pb[i].y);
            if (b5) sth2(Bd + bn[5] * 40 + 2 * bkp[5], pb[5].x, pb[5].y);
            __syncthreads();
        }
    }
    __syncthreads();

    // ---------------- epilogue ----------------
    __half* bufQ = smh;              // [64][136]
    __half* bufK = smh + 8704;       // [64][136]
    const int wz = warp % 6;
    const int proj = wz >> 1;        // 0=Q warps, 1=K warps, 2=V warps
    const int wml = (wz & 1) * 32;

    // pass 1: V -> bufQ region -> g_V
    if (proj == 2) {
#pragma unroll
        for (int mi = 0; mi < 2; mi++) {
            int rl = wml + mi * 16 + gid;
            float b0v = bv[rl], b1v = bv[rl + 8];
#pragma unroll
            for (int ni = 0; ni < 8; ni++) {
                int col = wn + ni * 8 + 2 * tig;
                sth2(bufQ + rl * 136 + col,       acc[mi][ni][0] + b0v, acc[mi][ni][1] + b0v);
                sth2(bufQ + (rl + 8) * 136 + col, acc[mi][ni][2] + b1v, acc[mi][ni][3] + b1v);
            }
        }
    }
    __syncthreads();
#pragma unroll
    for (int i = 0; i < 3; i++) {
        int v = tid + i * 384;
        if (v < 1024) {
            int row = v >> 4, c = v & 15;
            uint4 t = *reinterpret_cast<const uint4*>(bufQ + row * 136 + c * 8);
            *reinterpret_cast<uint4*>(g_V + ((size_t)b * CPD + row) * NN + n0 + c * 8) = t;
        }
    }
    __syncthreads();

    // pass 2: Q -> bufQ, K -> bufK (simultaneous, different buffers)
    if (proj < 2) {
        __half* dst = proj == 0 ? bufQ : bufK;
        const float* bias = proj == 0 ? bq : bk;
#pragma unroll
        for (int mi = 0; mi < 2; mi++) {
            int rl = wml + mi * 16 + gid;
            float b0v = bias[rl], b1v = bias[rl + 8];
#pragma unroll
            for (int ni = 0; ni < 8; ni++) {
                int col = wn + ni * 8 + 2 * tig;
                sth2(dst + rl * 136 + col,       acc[mi][ni][0] + b0v, acc[mi][ni][1] + b0v);
                sth2(dst + (rl + 8) * 136 + col, acc[mi][ni][2] + b1v, acc[mi][ni][3] + b1v);
            }
        }
    }
    __syncthreads();

    // E_part(64,64) = K(64ch x 128n) @ Q(64ch x 128n)^T, 8 warps (2m x 4n)
    if (warp < 8) {
        const int wmE = (warp & 1) * 32;
        const int wnE = (warp >> 1) * 16;
        float accE[2][2][4];
#pragma unroll
        for (int i = 0; i < 2; i++)
#pragma unroll
            for (int j = 0; j < 2; j++)
#pragma unroll
                for (int q = 0; q < 4; q++) accE[i][j][q] = 0.f;

        const uint32_t* A32 = reinterpret_cast<const uint32_t*>(bufK);
        const uint32_t* B32 = reinterpret_cast<const uint32_t*>(bufQ);
#pragma unroll
        for (int kk = 0; kk < 8; kk++) {
            uint32_t af[2][4], bf[2][2];
#pragma unroll
            for (int mi = 0; mi < 2; mi++) {
                int base = (wmE + mi * 16 + gid) * 68 + kk * 8 + tig;
                af[mi][0] = A32[base];
                af[mi][1] = A32[base + 8 * 68];
                af[mi][2] = A32[base + 4];
                af[mi][3] = A32[base + 8 * 68 + 4];
            }
#pragma unroll
            for (int ni = 0; ni < 2; ni++) {
                int base = (wnE + ni * 8 + gid) * 68 + kk * 8 + tig;
                bf[ni][0] = B32[base];
                bf[ni][1] = B32[base + 4];
            }
#pragma unroll
            for (int mi = 0; mi < 2; mi++)
#pragma unroll
                for (int ni = 0; ni < 2; ni++) mma16(accE[mi][ni], af[mi], bf[ni]);
        }

        float* P = g_P + (size_t)(b * 32 + blockIdx.x) * CPD * CPD;
#pragma unroll
        for (int mi = 0; mi < 2; mi++) {
            int r0 = wmE + mi * 16 + gid;
#pragma unroll
            for (int ni = 0; ni < 2; ni++) {
                int cc = wnE + ni * 8 + 2 * tig;
                *reinterpret_cast<float2*>(P + (size_t)r0 * CPD + cc) =
                    make_float2(accE[mi][ni][0], accE[mi][ni][1]);
                *reinterpret_cast<float2*>(P + (size_t)(r0 + 8) * CPD + cc) =
                    make_float2(accE[mi][ni][2], accE[mi][ni][3]);
            }
        }
    }
}

// ============================================================================
// K3: reduce 32 partials + softmax + M = Wo @ A (fp32 compute, fp16 store)
// grid (4 cgroups, 16 b), 512 threads
// ============================================================================
__global__ __launch_bounds__(512) void softmax_momix_kernel(const float* __restrict__ wo)
{
    __shared__ float A[64][68];
    __shared__ float Wos[64][68];
    const int cg = blockIdx.x, b = blockIdx.y, tid = threadIdx.x;

    for (int idx = tid; idx < 4096; idx += 512) {
        float ssum = 0.f;
#pragma unroll
        for (int p = 0; p < 32; p++)
            ssum += g_P[(size_t)(b * 32 + p) * 4096 + idx];
        A[idx >> 6][idx & 63] = ssum;
    }
    __syncthreads();
    if (tid < 64) {
        float m = -1e30f;
#pragma unroll
        for (int j = 0; j < 64; j++) m = fmaxf(m, A[tid][j]);
        float ssum = 0.f;
#pragma unroll
        for (int j = 0; j < 64; j++) {
            float e = __expf(A[tid][j] - m);
            A[tid][j] = e;
            ssum += e;
        }
        float inv = 1.f / ssum;
#pragma unroll
        for (int j = 0; j < 64; j++) A[tid][j] *= inv;
    }
    __syncthreads();

    const int cl = tid >> 3, jg = tid & 7;
    for (int ci = 0; ci < 2; ci++) {
        const int c0 = (cg * 2 + ci) * 64;
#pragma unroll
        for (int i = 0; i < 2; i++) {
            int v = tid + i * 512, m = v >> 4, kv = v & 15;
            *reinterpret_cast<float4*>(&Wos[m][kv * 4]) =
                *reinterpret_cast<const float4*>(wo + (size_t)(c0 + m) * CPD + kv * 4);
        }
        __syncthreads();

        float acc[8];
#pragma unroll
        for (int q = 0; q < 8; q++) acc[q] = 0.f;
#pragma unroll 8
        for (int o = 0; o < 64; o++) {
            float w = Wos[cl][o];
            const float4* ar = reinterpret_cast<const float4*>(&A[o][jg * 8]);
            float4 a0 = ar[0], a1 = ar[1];
            acc[0] += w * a0.x; acc[1] += w * a0.y; acc[2] += w * a0.z; acc[3] += w * a0.w;
            acc[4] += w * a1.x; acc[5] += w * a1.y; acc[6] += w * a1.z; acc[7] += w * a1.w;
        }
        __half2 h0 = __floats2half2_rn(acc[0], acc[1]);
        __half2 h1 = __floats2half2_rn(acc[2], acc[3]);
        __half2 h2 = __floats2half2_rn(acc[4], acc[5]);
        __half2 h3 = __floats2half2_rn(acc[6], acc[7]);
        uint4 u;
        u.x = *reinterpret_cast<uint32_t*>(&h0);
        u.y = *reinterpret_cast<uint32_t*>(&h1);
        u.z = *reinterpret_cast<uint32_t*>(&h2);
        u.w = *reinterpret_cast<uint32_t*>(&h3);
        *reinterpret_cast<uint4*>(g_M + ((size_t)b * CC + c0 + cl) * CPD + jg * 8) = u;
        __syncthreads();
    }
}

// ============================================================================
// K4: Y = gamma*(M @ V + bo) + X.  [fp16 mma]
// grid (32 n-tiles, 16 b, 2 c-halves), 256 threads (8 warps: 2m x 4n).
// Each CTA: V tile resident (transposed once), 4 c-chunks, M double-buffered,
// X prefetched into registers before MMA to hide DRAM latency under HMMA.
// ============================================================================
__global__ __launch_bounds__(256) void out_kernel(
    const float* __restrict__ x, const float* __restrict__ bo,
    const float* __restrict__ gamma, float* __restrict__ y)
{
    __shared__ __half sm4[22528];
    __half* Vt = sm4;                 // [128][72]
    __half* Ms = sm4 + 9216;          // [2][64][72]
    __half* Vraw = sm4 + 13824;       // [64][136] (overlays Ms[1] pre-loop)

    const int n0 = blockIdx.x * 128, b = blockIdx.y;
    const int cb = blockIdx.z * 256;  // c-chunk base for this CTA
    const int tid = threadIdx.x, lane = tid & 31, warp = tid >> 5;
    const int wm = (warp & 1) * 32, wn = (warp >> 1) * 32;
    const int gid = lane >> 2, tig = lane & 3;

    // group0: Vraw + M chunk 0
#pragma unroll
    for (int i = 0; i < 4; i++) {
        int v = tid + i * 256, r = v >> 4, sg = v & 15;
        cp_async16(Vraw + r * 136 + sg * 8,
                   g_V + ((size_t)b * CPD + r) * NN + n0 + sg * 8);
    }
#pragma unroll
    for (int i = 0; i < 2; i++) {
        int v = tid + i * 256, r = v >> 3, sg = v & 7;
        cp_async16(Ms + r * 72 + sg * 8,
                   g_M + ((size_t)b * CC + cb + r) * CPD + sg * 8);
    }
    CP_COMMIT();
    CP_WAIT(0);
    __syncthreads();

    // transpose Vraw[cp][n] -> Vt[n][cp]
    {
        const int n = tid & 127, cph = tid >> 7;
#pragma unroll
        for (int j = 0; j < 16; j++) {
            int cp = 2 * cph + 4 * j;
            __half a = Vraw[cp * 136 + n];
            __half c = Vraw[(cp + 1) * 136 + n];
            *reinterpret_cast<__half2*>(Vt + n * 72 + cp) = __halves2half2(a, c);
        }
    }
    __syncthreads();

    const float g = gamma[0];

    for (int ch = 0; ch < 4; ch++) {
        const int buf = ch & 1;
        const int c0 = cb + ch * 64;
        if (ch < 3) {
            __half* Md = Ms + (buf ^ 1) * 4608;
#pragma unroll
            for (int i = 0; i < 2; i++) {
                int v = tid + i * 256, r = v >> 3, sg = v & 7;
                cp_async16(Md + r * 72 + sg * 8,
                           g_M + ((size_t)b * CC + c0 + 64 + r) * CPD + sg * 8);
            }
            CP_COMMIT();
            CP_WAIT(1);
        } else {
            CP_WAIT(0);
        }
        __syncthreads();

        // prefetch X for this chunk into registers (hides under MMA)
        float2 xp0[2][4], xp1[2][4];
#pragma unroll
        for (int mi = 0; mi < 2; mi++) {
            int r0 = wm + mi * 16 + gid;
#pragma unroll
            for (int ni = 0; ni < 4; ni++) {
                int nn = n0 + wn + ni * 8 + 2 * tig;
                xp0[mi][ni] = *reinterpret_cast<const float2*>(
                    x + ((size_t)b * CC + c0 + r0) * NN + nn);
                xp1[mi][ni] = *reinterpret_cast<const float2*>(
                    x + ((size_t)b * CC + c0 + r0 + 8) * NN + nn);
            }
        }

        float acc[2][4][4];
#pragma unroll
        for (int i = 0; i < 2; i++)
#pragma unroll
            for (int j = 0; j < 4; j++)
#pragma unroll
                for (int q = 0; q < 4; q++) acc[i][j][q] = 0.f;

        const uint32_t* A32 = reinterpret_cast<const uint32_t*>(Ms + buf * 4608);
        const uint32_t* B32 = reinterpret_cast<const uint32_t*>(Vt);
#pragma unroll
        for (int kk = 0; kk < 4; kk++) {
            uint32_t af[2][4], bf[4][2];
#pragma unroll
            for (int mi = 0; mi < 2; mi++) {
                int base = (wm + mi * 16 + gid) * 36 + kk * 8 + tig;
                af[mi][0] = A32[base];
                af[mi][1] = A32[base + 8 * 36];
                af[mi][2] = A32[base + 4];
                af[mi][3] = A32[base + 8 * 36 + 4];
            }
#pragma unroll
            for (int ni = 0; ni < 4; ni++) {
                int base = (wn + ni * 8 + gid) * 36 + kk * 8 + tig;
                bf[ni][0] = B32[base];
                bf[ni][1] = B32[base + 4];
            }
#pragma unroll
            for (int mi = 0; mi < 2; mi++)
#pragma unroll
                for (int ni = 0; ni < 4; ni++) mma16(acc[mi][ni], af[mi], bf[ni]);
        }

#pragma unroll
        for (int mi = 0; mi < 2; mi++) {
            int r0 = wm + mi * 16 + gid;
            int ch0 = c0 + r0, ch1 = c0 + r0 + 8;
            float bo0 = bo[ch0], bo1 = bo[ch1];
#pragma unroll
            for (int ni = 0; ni < 4; ni++) {
                int nn = n0 + wn + ni * 8 + 2 * tig;
                size_t off0 = ((size_t)b * CC + ch0) * NN + nn;
                size_t off1 = ((size_t)b * CC + ch1) * NN + nn;
                float2 o0, o1;
                o0.x = g * (acc[mi][ni][0] + bo0) + xp0[mi][ni].x;
                o0.y = g * (acc[mi][ni][1] + bo0) + xp0[mi][ni].y;
                o1.x = g * (acc[mi][ni][2] + bo1) + xp1[mi][ni].x;
                o1.y = g * (acc[mi][ni][3] + bo1) + xp1[mi][ni].y;
                *reinterpret_cast<float2*>(y + off0) = o0;
                *reinterpret_cast<float2*>(y + off1) = o1;
            }
        }
        __syncthreads();
    }
}

// ============================================================================
extern "C" void kernel_launch(void* const* d_in, const int* in_sizes, int n_in,
                              void* d_out, int out_size)
{
    const float* x  = (const float*)d_in[0];
    const float* wq = (const float*)d_in[1];
    const float* bq = (const float*)d_in[2];
    const float* wk = (const float*)d_in[3];
    const float* bk = (const float*)d_in[4];
    const float* wv = (const float*)d_in[5];
    const float* bv = (const float*)d_in[6];
    const float* wo = (const float*)d_in[7];
    const float* bo = (const float*)d_in[8];
    const float* gm = (const float*)d_in[9];
    float* y = (float*)d_out;

    static int inited = 0;
    if (!inited) {
        cudaFuncSetAttribute(qkv_energy_kernel, cudaFuncAttributeMaxDynamicSharedMemorySize,
                             K1_SMEMB);
        inited = 1;
    }

    qkv_energy_kernel<<<dim3(32, 16), 384, K1_SMEMB>>>(x, wq, bq, wk, bk, wv, bv);
    softmax_momix_kernel<<<dim3(4, 16), 512>>>(wo);
    out_kernel<<<dim3(32, 16, 2), 256>>>(x, bo, gm, y);
}

// round 6
// speedup vs baseline: 1.5371x; 1.0395x over previous
#include <cuda_runtime.h>
#include <cuda_fp16.h>
#include <cstdint>

#define NB 16
#define CC 512
#define CPD 64
#define NN 4096

// scratch (static __device__ — no allocation)
__device__ __half g_V[(size_t)NB * CPD * NN];
__device__ float  g_P[(size_t)NB * 32 * CPD * CPD]; // energy partials (32 n-slices)
__device__ __half g_M[NB * CC * CPD];               // M = Wo @ A (fp16)
__device__ __half g_W[192 * 512];                   // fp16 Wqkv (Q rows 0-63, K 64-127, V 128-191)

__device__ __forceinline__ void cp_async16(void* smem, const void* gmem) {
    uint32_t s = (uint32_t)__cvta_generic_to_shared(smem);
    asm volatile("cp.async.cg.shared.global [%0], [%1], 16;\n" :: "r"(s), "l"(gmem));
}
#define CP_COMMIT() asm volatile("cp.async.commit_group;\n" ::: "memory")
#define CP_WAIT(n)  asm volatile("cp.async.wait_group %0;\n" :: "n"(n) : "memory")

// fp16 mma: D(f32) += A(f16,row) * B(f16,col), m16n8k16
__device__ __forceinline__ void mma16(float c[4], const uint32_t a[4], const uint32_t b[2]) {
    asm volatile(
        "mma.sync.aligned.m16n8k16.row.col.f32.f16.f16.f32 "
        "{%0,%1,%2,%3},{%4,%5,%6,%7},{%8,%9},{%0,%1,%2,%3};"
        : "+f"(c[0]), "+f"(c[1]), "+f"(c[2]), "+f"(c[3])
        : "r"(a[0]), "r"(a[1]), "r"(a[2]), "r"(a[3]), "r"(b[0]), "r"(b[1]));
}

__device__ __forceinline__ void sth2(__half* p, float a, float b) {
    *reinterpret_cast<__half2*>(p) = __floats2half2_rn(a, b);
}

// ============================================================================
// K0: convert Wqkv -> fp16 g_W. grid 96, 256 threads
// ============================================================================
__global__ __launch_bounds__(256) void wconv_kernel(
    const float* __restrict__ wq, const float* __restrict__ wk, const float* __restrict__ wv)
{
    int f = (blockIdx.x * 256 + threadIdx.x) * 4;   // 0..98300
    int r = f >> 9, c = f & 511;
    const float* w = r < 64 ? wq + (size_t)r * 512
                   : r < 128 ? wk + (size_t)(r - 64) * 512
                             : wv + (size_t)(r - 128) * 512;
    float4 t = *reinterpret_cast<const float4*>(w + c);
    __half2 h0 = __floats2half2_rn(t.x, t.y);
    __half2 h1 = __floats2half2_rn(t.z, t.w);
    uint2 u;
    u.x = *reinterpret_cast<uint32_t*>(&h0);
    u.y = *reinterpret_cast<uint32_t*>(&h1);
    *reinterpret_cast<uint2*>(g_W + (size_t)r * 512 + c) = u;
}

// ============================================================================
// K1: fused QKV + energy. 512 threads (16 warps: 4m x 4n), tile 192x128, BK=32
// A fp16 via cp.async from g_W; X staged fp32 via cp.async, transposed->fp16 B.
// byte offsets into dynamic smem:
//   A0 @0 (15360), A1 @15360 | S0 @30720 (16896), S1 @47616 | B0 @64512 (10240), B1 @74752
//   epilogue overlay: bufQ @0, bufK @17408, bufV @34816 (each 64x136 halves)
// ============================================================================
#define SB_A0 0
#define SB_A1 15360
#define SB_S0 30720
#define SB_S1 47616
#define SB_B0 64512
#define SB_B1 74752
#define K1_SMEMB 84992

__global__ __launch_bounds__(512, 1) void qkv_energy_kernel(
    const float* __restrict__ x,
    const float* __restrict__ bq, const float* __restrict__ bk, const float* __restrict__ bv)
{
    extern __shared__ char smc[];
    const int b = blockIdx.y;
    const int n0 = blockIdx.x * 128;
    const float* Xb = x + (size_t)b * CC * NN;

    const int tid = threadIdx.x;
    const int lane = tid & 31, warp = tid >> 5;
    const int wm = (warp & 3) * 48;      // m-offset in 192
    const int wn = (warp >> 2) * 32;     // n-offset in 128
    const int gid = lane >> 2, tig = lane & 3;

    // A cp coords: 768 cp/stage (16B = 8 halves each): r=v>>2, kv=v&3
    const int av = tid;                            // first 512
    const int av1 = tid + 512;                     // pred < 768
    // S cp coords: 1024 cp/stage: k=v>>5, nv=v&31
    // transpose coords: n = tid&127, kg = tid>>7

    float acc[3][4][4];
#pragma unroll
    for (int i = 0; i < 3; i++)
#pragma unroll
        for (int j = 0; j < 4; j++)
#pragma unroll
            for (int q = 0; q < 4; q++) acc[i][j][q] = 0.f;

    // prologue: stages 0 and 1, two commit groups
#pragma unroll
    for (int st = 0; st < 2; st++) {
        const int k0 = st * 32;
        char* Ad = smc + (st ? SB_A1 : SB_A0);
        char* Sd = smc + (st ? SB_S1 : SB_S0);
        {
            int r = av >> 2, kv = av & 3;
            cp_async16(Ad + r * 80 + kv * 16, g_W + (size_t)r * 512 + k0 + kv * 8);
            if (av1 < 768) {
                int r1 = av1 >> 2, kv1 = av1 & 3;
                cp_async16(Ad + r1 * 80 + kv1 * 16, g_W + (size_t)r1 * 512 + k0 + kv1 * 8);
            }
        }
#pragma unroll
        for (int i = 0; i < 2; i++) {
            int v = tid + i * 512, k = v >> 5, nv = v & 31;
            cp_async16(Sd + k * 528 + nv * 16, Xb + (size_t)(k0 + k) * NN + n0 + nv * 4);
        }
        CP_COMMIT();
    }

    for (int kt = 0; kt < 16; kt++) {
        const int buf = kt & 1;
        if (kt < 15) { CP_WAIT(1); } else { CP_WAIT(0); }
        __syncthreads();

        // transpose S[buf] (fp32 [32][132]) -> B[buf] (fp16 [128][40])
        {
            const float* S = reinterpret_cast<const float*>(smc + (buf ? SB_S1 : SB_S0));
            __half* Bd = reinterpret_cast<__half*>(smc + (buf ? SB_B1 : SB_B0));
            const int n = tid & 127, kg = tid >> 7;
            const float* col = S + n;
            float v0 = col[(kg * 8 + 0) * 132], v1 = col[(kg * 8 + 1) * 132];
            float v2 = col[(kg * 8 + 2) * 132], v3 = col[(kg * 8 + 3) * 132];
            float v4 = col[(kg * 8 + 4) * 132], v5 = col[(kg * 8 + 5) * 132];
            float v6 = col[(kg * 8 + 6) * 132], v7 = col[(kg * 8 + 7) * 132];
            __half2 h0 = __floats2half2_rn(v0, v1), h1 = __floats2half2_rn(v2, v3);
            __half2 h2 = __floats2half2_rn(v4, v5), h3 = __floats2half2_rn(v6, v7);
            uint4 u;
            u.x = *reinterpret_cast<uint32_t*>(&h0);
            u.y = *reinterpret_cast<uint32_t*>(&h1);
            u.z = *reinterpret_cast<uint32_t*>(&h2);
            u.w = *reinterpret_cast<uint32_t*>(&h3);
            *reinterpret_cast<uint4*>(Bd + n * 40 + kg * 8) = u;
        }
        __syncthreads();

        // MMA on A[buf], B[buf]
        const uint32_t* A32 = reinterpret_cast<const uint32_t*>(smc + (buf ? SB_A1 : SB_A0));
        const uint32_t* B32 = reinterpret_cast<const uint32_t*>(smc + (buf ? SB_B1 : SB_B0));
#pragma unroll
        for (int kk = 0; kk < 2; kk++) {
            uint32_t af[3][4], bf[4][2];
#pragma unroll
            for (int mi = 0; mi < 3; mi++) {
                int base = (wm + mi * 16 + gid) * 20 + kk * 8 + tig;
                af[mi][0] = A32[base];
                af[mi][1] = A32[base + 8 * 20];
                af[mi][2] = A32[base + 4];
                af[mi][3] = A32[base + 8 * 20 + 4];
            }
#pragma unroll
            for (int ni = 0; ni < 4; ni++) {
                int base = (wn + ni * 8 + gid) * 20 + kk * 8 + tig;
                bf[ni][0] = B32[base];
                bf[ni][1] = B32[base + 4];
            }
#pragma unroll
            for (int mi = 0; mi < 3; mi++)
#pragma unroll
                for (int ni = 0; ni < 4; ni++) mma16(acc[mi][ni], af[mi], bf[ni]);
        }
        __syncthreads();   // frag reads of A[buf]/B[buf] done; S[buf] free

        if (kt + 2 < 16) {
            const int k0 = (kt + 2) * 32;
            char* Ad = smc + (buf ? SB_A1 : SB_A0);
            char* Sd = smc + (buf ? SB_S1 : SB_S0);
            {
                int r = av >> 2, kv = av & 3;
                cp_async16(Ad + r * 80 + kv * 16, g_W + (size_t)r * 512 + k0 + kv * 8);
                if (av1 < 768) {
                    int r1 = av1 >> 2, kv1 = av1 & 3;
                    cp_async16(Ad + r1 * 80 + kv1 * 16, g_W + (size_t)r1 * 512 + k0 + kv1 * 8);
                }
            }
#pragma unroll
            for (int i = 0; i < 2; i++) {
                int v = tid + i * 512, k = v >> 5, nv = v & 31;
                cp_async16(Sd + k * 528 + nv * 16, Xb + (size_t)(k0 + k) * NN + n0 + nv * 4);
            }
            CP_COMMIT();
        }
    }

    // ---------------- epilogue ----------------
    __half* bufQ = reinterpret_cast<__half*>(smc);           // [64][136]
    __half* bufK = reinterpret_cast<__half*>(smc + 17408);
    __half* bufV = reinterpret_cast<__half*>(smc + 34816);

    // route acc tiles (+bias) to per-proj buffers
#pragma unroll
    for (int mi = 0; mi < 3; mi++) {
        int row = wm + mi * 16;
        int p = row >> 6;
        int lr = (row & 63) + gid;
        const float* bias = p == 0 ? bq : (p == 1 ? bk : bv);
        __half* dst = p == 0 ? bufQ : (p == 1 ? bufK : bufV);
        float b0v = bias[lr], b1v = bias[lr + 8];
#pragma unroll
        for (int ni = 0; ni < 4; ni++) {
            int col = wn + ni * 8 + 2 * tig;
            sth2(dst + lr * 136 + col,       acc[mi][ni][0] + b0v, acc[mi][ni][1] + b0v);
            sth2(dst + (lr + 8) * 136 + col, acc[mi][ni][2] + b1v, acc[mi][ni][3] + b1v);
        }
    }
    __syncthreads();

    // V -> global
#pragma unroll
    for (int i = 0; i < 2; i++) {
        int v = tid + i * 512;
        int row = v >> 4, c = v & 15;
        uint4 t = *reinterpret_cast<const uint4*>(bufV + row * 136 + c * 8);
        *reinterpret_cast<uint4*>(g_V + ((size_t)b * CPD + row) * NN + n0 + c * 8) = t;
    }

    // energy: E(64,64) = K(64x128) @ Q(64x128)^T, 16 warps (4m x 4n)
    {
        const int wmE = (warp & 3) * 16;
        const int wnE = (warp >> 2) * 16;
        float accE[2][4];
#pragma unroll
        for (int j = 0; j < 2; j++)
#pragma unroll
            for (int q = 0; q < 4; q++) accE[j][q] = 0.f;

        const uint32_t* A32 = reinterpret_cast<const uint32_t*>(bufK);
        const uint32_t* B32 = reinterpret_cast<const uint32_t*>(bufQ);
#pragma unroll
        for (int kk = 0; kk < 8; kk++) {
            uint32_t af[4], bf[2][2];
            int base = (wmE + gid) * 68 + kk * 8 + tig;
            af[0] = A32[base];
            af[1] = A32[base + 8 * 68];
            af[2] = A32[base + 4];
            af[3] = A32[base + 8 * 68 + 4];
#pragma unroll
            for (int ni = 0; ni < 2; ni++) {
                int bb = (wnE + ni * 8 + gid) * 68 + kk * 8 + tig;
                bf[ni][0] = B32[bb];
                bf[ni][1] = B32[bb + 4];
            }
#pragma unroll
            for (int ni = 0; ni < 2; ni++) mma16(accE[ni], af, bf[ni]);
        }

        float* P = g_P + (size_t)(b * 32 + blockIdx.x) * CPD * CPD;
        int r0 = wmE + gid;
#pragma unroll
        for (int ni = 0; ni < 2; ni++) {
            int cc = wnE + ni * 8 + 2 * tig;
            *reinterpret_cast<float2*>(P + (size_t)r0 * CPD + cc) =
                make_float2(accE[ni][0], accE[ni][1]);
            *reinterpret_cast<float2*>(P + (size_t)(r0 + 8) * CPD + cc) =
                make_float2(accE[ni][2], accE[ni][3]);
        }
    }
}

// ============================================================================
// K3: reduce 32 partials + softmax + M = Wo @ A (fp32 compute, fp16 store)
// grid (4 cgroups, 16 b), 512 threads
// ============================================================================
__global__ __launch_bounds__(512) void softmax_momix_kernel(const float* __restrict__ wo)
{
    __shared__ float A[64][68];
    __shared__ float Wos[64][68];
    const int cg = blockIdx.x, b = blockIdx.y, tid = threadIdx.x;

    for (int idx = tid; idx < 4096; idx += 512) {
        float ssum = 0.f;
#pragma unroll
        for (int p = 0; p < 32; p++)
            ssum += g_P[(size_t)(b * 32 + p) * 4096 + idx];
        A[idx >> 6][idx & 63] = ssum;
    }
    __syncthreads();
    if (tid < 64) {
        float m = -1e30f;
#pragma unroll
        for (int j = 0; j < 64; j++) m = fmaxf(m, A[tid][j]);
        float ssum = 0.f;
#pragma unroll
        for (int j = 0; j < 64; j++) {
            float e = __expf(A[tid][j] - m);
            A[tid][j] = e;
            ssum += e;
        }
        float inv = 1.f / ssum;
#pragma unroll
        for (int j = 0; j < 64; j++) A[tid][j] *= inv;
    }
    __syncthreads();

    const int cl = tid >> 3, jg = tid & 7;
    for (int ci = 0; ci < 2; ci++) {
        const int c0 = (cg * 2 + ci) * 64;
#pragma unroll
        for (int i = 0; i < 2; i++) {
            int v = tid + i * 512, m = v >> 4, kv = v & 15;
            *reinterpret_cast<float4*>(&Wos[m][kv * 4]) =
                *reinterpret_cast<const float4*>(wo + (size_t)(c0 + m) * CPD + kv * 4);
        }
        __syncthreads();

        float acc[8];
#pragma unroll
        for (int q = 0; q < 8; q++) acc[q] = 0.f;
#pragma unroll 8
        for (int o = 0; o < 64; o++) {
            float w = Wos[cl][o];
            const float4* ar = reinterpret_cast<const float4*>(&A[o][jg * 8]);
            float4 a0 = ar[0], a1 = ar[1];
            acc[0] += w * a0.x; acc[1] += w * a0.y; acc[2] += w * a0.z; acc[3] += w * a0.w;
            acc[4] += w * a1.x; acc[5] += w * a1.y; acc[6] += w * a1.z; acc[7] += w * a1.w;
        }
        __half2 h0 = __floats2half2_rn(acc[0], acc[1]);
        __half2 h1 = __floats2half2_rn(acc[2], acc[3]);
        __half2 h2 = __floats2half2_rn(acc[4], acc[5]);
        __half2 h3 = __floats2half2_rn(acc[6], acc[7]);
        uint4 u;
        u.x = *reinterpret_cast<uint32_t*>(&h0);
        u.y = *reinterpret_cast<uint32_t*>(&h1);
        u.z = *reinterpret_cast<uint32_t*>(&h2);
        u.w = *reinterpret_cast<uint32_t*>(&h3);
        *reinterpret_cast<uint4*>(g_M + ((size_t)b * CC + c0 + cl) * CPD + jg * 8) = u;
        __syncthreads();
    }
}

// ============================================================================
// K4: Y = gamma*(M @ V + bo) + X.  [fp16 mma]
// grid (32 n-tiles, 16 b, 4 c-quarters), 256 threads (8 warps: 2m x 4n).
// Each CTA: V tile resident (transposed once), 2 c-chunks, M double-buffered,
// X prefetched into registers before MMA.
// ============================================================================
__global__ __launch_bounds__(256) void out_kernel(
    const float* __restrict__ x, const float* __restrict__ bo,
    const float* __restrict__ gamma, float* __restrict__ y)
{
    __shared__ __half sm4[22528];
    __half* Vt = sm4;                 // [128][72]
    __half* Ms = sm4 + 9216;          // [2][64][72]
    __half* Vraw = sm4 + 13824;       // [64][136] (overlays Ms[1] pre-loop)

    const int n0 = blockIdx.x * 128, b = blockIdx.y;
    const int cb = blockIdx.z * 128;  // c-base for this CTA (2 chunks of 64)
    const int tid = threadIdx.x, lane = tid & 31, warp = tid >> 5;
    const int wm = (warp & 1) * 32, wn = (warp >> 1) * 32;
    const int gid = lane >> 2, tig = lane & 3;

    // group0: Vraw + M chunk 0
#pragma unroll
    for (int i = 0; i < 4; i++) {
        int v = tid + i * 256, r = v >> 4, sg = v & 15;
        cp_async16(Vraw + r * 136 + sg * 8,
                   g_V + ((size_t)b * CPD + r) * NN + n0 + sg * 8);
    }
#pragma unroll
    for (int i = 0; i < 2; i++) {
        int v = tid + i * 256, r = v >> 3, sg = v & 7;
        cp_async16(Ms + r * 72 + sg * 8,
                   g_M + ((size_t)b * CC + cb + r) * CPD + sg * 8);
    }
    CP_COMMIT();
    CP_WAIT(0);
    __syncthreads();

    // transpose Vraw[cp][n] -> Vt[n][cp]
    {
        const int n = tid & 127, cph = tid >> 7;
#pragma unroll
        for (int j = 0; j < 16; j++) {
            int cp = 2 * cph + 4 * j;
            __half a = Vraw[cp * 136 + n];
            __half c = Vraw[(cp + 1) * 136 + n];
            *reinterpret_cast<__half2*>(Vt + n * 72 + cp) = __halves2half2(a, c);
        }
    }
    __syncthreads();

    const float g = gamma[0];

    for (int ch = 0; ch < 2; ch++) {
        const int buf = ch & 1;
        const int c0 = cb + ch * 64;
        if (ch < 1) {
            __half* Md = Ms + 4608;
#pragma unroll
            for (int i = 0; i < 2; i++) {
                int v = tid + i * 256, r = v >> 3, sg = v & 7;
                cp_async16(Md + r * 72 + sg * 8,
                           g_M + ((size_t)b * CC + c0 + 64 + r) * CPD + sg * 8);
            }
            CP_COMMIT();
            CP_WAIT(1);
        } else {
            CP_WAIT(0);
        }
        __syncthreads();

        // prefetch X for this chunk into registers (hides under MMA)
        float2 xp0[2][4], xp1[2][4];
#pragma unroll
        for (int mi = 0; mi < 2; mi++) {
            int r0 = wm + mi * 16 + gid;
#pragma unroll
            for (int ni = 0; ni < 4; ni++) {
                int nn = n0 + wn + ni * 8 + 2 * tig;
                xp0[mi][ni] = *reinterpret_cast<const float2*>(
                    x + ((size_t)b * CC + c0 + r0) * NN + nn);
                xp1[mi][ni] = *reinterpret_cast<const float2*>(
                    x + ((size_t)b * CC + c0 + r0 + 8) * NN + nn);
            }
        }

        float acc[2][4][4];
#pragma unroll
        for (int i = 0; i < 2; i++)
#pragma unroll
            for (int j = 0; j < 4; j++)
#pragma unroll
                for (int q = 0; q < 4; q++) acc[i][j][q] = 0.f;

        const uint32_t* A32 = reinterpret_cast<const uint32_t*>(Ms + buf * 4608);
        const uint32_t* B32 = reinterpret_cast<const uint32_t*>(Vt);
#pragma unroll
        for (int kk = 0; kk < 4; kk++) {
            uint32_t af[2][4], bf[4][2];
#pragma unroll
            for (int mi = 0; mi < 2; mi++) {
                int base = (wm + mi * 16 + gid) * 36 + kk * 8 + tig;
                af[mi][0] = A32[base];
                af[mi][1] = A32[base + 8 * 36];
                af[mi][2] = A32[base + 4];
                af[mi][3] = A32[base + 8 * 36 + 4];
            }
#pragma unroll
            for (int ni = 0; ni < 4; ni++) {
                int base = (wn + ni * 8 + gid) * 36 + kk * 8 + tig;
                bf[ni][0] = B32[base];
                bf[ni][1] = B32[base + 4];
            }
#pragma unroll
            for (int mi = 0; mi < 2; mi++)
#pragma unroll
                for (int ni = 0; ni < 4; ni++) mma16(acc[mi][ni], af[mi], bf[ni]);
        }

#pragma unroll
        for (int mi = 0; mi < 2; mi++) {
            int r0 = wm + mi * 16 + gid;
            int ch0 = c0 + r0, ch1 = c0 + r0 + 8;
            float bo0 = bo[ch0], bo1 = bo[ch1];
#pragma unroll
            for (int ni = 0; ni < 4; ni++) {
                int nn = n0 + wn + ni * 8 + 2 * tig;
                size_t off0 = ((size_t)b * CC + ch0) * NN + nn;
                size_t off1 = ((size_t)b * CC + ch1) * NN + nn;
                float2 o0, o1;
                o0.x = g * (acc[mi][ni][0] + bo0) + xp0[mi][ni].x;
                o0.y = g * (acc[mi][ni][1] + bo0) + xp0[mi][ni].y;
                o1.x = g * (acc[mi][ni][2] + bo1) + xp1[mi][ni].x;
                o1.y = g * (acc[mi][ni][3] + bo1) + xp1[mi][ni].y;
                *reinterpret_cast<float2*>(y + off0) = o0;
                *reinterpret_cast<float2*>(y + off1) = o1;
            }
        }
        __syncthreads();
    }
}

// ============================================================================
extern "C" void kernel_launch(void* const* d_in, const int* in_sizes, int n_in,
                              void* d_out, int out_size)
{
    const float* x  = (const float*)d_in[0];
    const float* wq = (const float*)d_in[1];
    const float* bq = (const float*)d_in[2];
    const float* wk = (const float*)d_in[3];
    const float* bk = (const float*)d_in[4];
    const float* wv = (const float*)d_in[5];
    const float* bv = (const float*)d_in[6];
    const float* wo = (const float*)d_in[7];
    const float* bo = (const float*)d_in[8];
    const float* gm = (const float*)d_in[9];
    float* y = (float*)d_out;

    static int inited = 0;
    if (!inited) {
        cudaFuncSetAttribute(qkv_energy_kernel, cudaFuncAttributeMaxDynamicSharedMemorySize,
                             K1_SMEMB);
        inited = 1;
    }

    wconv_kernel<<<96, 256>>>(wq, wk, wv);
    qkv_energy_kernel<<<dim3(32, 16), 512, K1_SMEMB>>>(x, bq, bk, bv);
    softmax_momix_kernel<<<dim3(4, 16), 512>>>(wo);
    out_kernel<<<dim3(32, 16, 4), 256>>>(x, bo, gm, y);
}

// round 7
// speedup vs baseline: 1.5623x; 1.0164x over previous
#include <cuda_runtime.h>
#include <cuda_fp16.h>
#include <cstdint>

#define NB 16
#define CC 512
#define CPD 64
#define NN 4096

// scratch (static __device__ — no allocation)
__device__ __half g_V[(size_t)NB * CPD * NN];
__device__ float  g_P[(size_t)NB * 32 * CPD * CPD]; // energy partials (32 n-slices)
__device__ __half g_M[NB * CC * CPD];               // M = Wo @ A (fp16)
__device__ __half g_W[192 * 512];                   // fp16 Wqkv

__device__ __forceinline__ void cp_async16(void* smem, const void* gmem) {
    uint32_t s = (uint32_t)__cvta_generic_to_shared(smem);
    asm volatile("cp.async.cg.shared.global [%0], [%1], 16;\n" :: "r"(s), "l"(gmem));
}
#define CP_COMMIT() asm volatile("cp.async.commit_group;\n" ::: "memory")
#define CP_WAIT(n)  asm volatile("cp.async.wait_group %0;\n" :: "n"(n) : "memory")

__device__ __forceinline__ void mma16(float c[4], const uint32_t a[4], const uint32_t b[2]) {
    asm volatile(
        "mma.sync.aligned.m16n8k16.row.col.f32.f16.f16.f32 "
        "{%0,%1,%2,%3},{%4,%5,%6,%7},{%8,%9},{%0,%1,%2,%3};"
        : "+f"(c[0]), "+f"(c[1]), "+f"(c[2]), "+f"(c[3])
        : "r"(a[0]), "r"(a[1]), "r"(a[2]), "r"(a[3]), "r"(b[0]), "r"(b[1]));
}

__device__ __forceinline__ void sth2(__half* p, float a, float b) {
    *reinterpret_cast<__half2*>(p) = __floats2half2_rn(a, b);
}

// ============================================================================
// K0: convert Wqkv -> fp16 g_W. grid 96, 256 threads
// ============================================================================
__global__ __launch_bounds__(256) void wconv_kernel(
    const float* __restrict__ wq, const float* __restrict__ wk, const float* __restrict__ wv)
{
    int f = (blockIdx.x * 256 + threadIdx.x) * 4;
    int r = f >> 9, c = f & 511;
    const float* w = r < 64 ? wq + (size_t)r * 512
                   : r < 128 ? wk + (size_t)(r - 64) * 512
                             : wv + (size_t)(r - 128) * 512;
    float4 t = *reinterpret_cast<const float4*>(w + c);
    __half2 h0 = __floats2half2_rn(t.x, t.y);
    __half2 h1 = __floats2half2_rn(t.z, t.w);
    uint2 u;
    u.x = *reinterpret_cast<uint32_t*>(&h0);
    u.y = *reinterpret_cast<uint32_t*>(&h1);
    *reinterpret_cast<uint2*>(g_W + (size_t)r * 512 + c) = u;
}

// ============================================================================
// K1: fused QKV + energy. 512 threads (16 warps: 4m x 4n), tile 192x128, BK=32
// Triple-buffered A/S (cp.async), double-buffered B (transposed fp16 X).
// ONE __syncthreads per iteration: transpose(stage kt+1) runs concurrently
// with MMA(stage kt) — disjoint buffers.
// byte offsets: A slots @0,15360,30720 | S slots @46080,62976,79872
//               B0 @96768, B1 @107008  (total 117248)
// epilogue overlay: bufQ @0, bufK @17408, bufV @34816 (each 64x136 halves)
// ============================================================================
#define K1_AS(i) ((i) * 15360)
#define K1_SS(i) (46080 + (i) * 16896)
#define K1_BS(i) (96768 + (i) * 10240)
#define K1_SMEMB 117248

__global__ __launch_bounds__(512, 1) void qkv_energy_kernel(
    const float* __restrict__ x,
    const float* __restrict__ bq, const float* __restrict__ bk, const float* __restrict__ bv)
{
    extern __shared__ char smc[];
    const int b = blockIdx.y;
    const int n0 = blockIdx.x * 128;
    const float* Xb = x + (size_t)b * CC * NN;

    const int tid = threadIdx.x;
    const int lane = tid & 31, warp = tid >> 5;
    const int wm = (warp & 3) * 48;
    const int wn = (warp >> 2) * 32;
    const int gid = lane >> 2, tig = lane & 3;

    const int av = tid, av1 = tid + 512;

    float acc[3][4][4];
#pragma unroll
    for (int i = 0; i < 3; i++)
#pragma unroll
        for (int j = 0; j < 4; j++)
#pragma unroll
            for (int q = 0; q < 4; q++) acc[i][j][q] = 0.f;

    // prologue: issue stages 0,1,2 (three groups)
#pragma unroll
    for (int st = 0; st < 3; st++) {
        const int k0 = st * 32;
        char* Ad = smc + K1_AS(st);
        char* Sd = smc + K1_SS(st);
        {
            int r = av >> 2, kv = av & 3;
            cp_async16(Ad + r * 80 + kv * 16, g_W + (size_t)r * 512 + k0 + kv * 8);
            if (av1 < 768) {
                int r1 = av1 >> 2, kv1 = av1 & 3;
                cp_async16(Ad + r1 * 80 + kv1 * 16, g_W + (size_t)r1 * 512 + k0 + kv1 * 8);
            }
        }
#pragma unroll
        for (int i = 0; i < 2; i++) {
            int v = tid + i * 512, k = v >> 5, nv = v & 31;
            cp_async16(Sd + k * 528 + nv * 16, Xb + (size_t)(k0 + k) * NN + n0 + nv * 4);
        }
        CP_COMMIT();
    }
    CP_WAIT(2);           // stage 0 arrived
    __syncthreads();
    // transpose stage0 -> B0
    {
        const float* S = reinterpret_cast<const float*>(smc + K1_SS(0));
        __half* Bd = reinterpret_cast<__half*>(smc + K1_BS(0));
        const int n = tid & 127, kg = tid >> 7;
        const float* col = S + n;
        float v0 = col[(kg * 8 + 0) * 132], v1 = col[(kg * 8 + 1) * 132];
        float v2 = col[(kg * 8 + 2) * 132], v3 = col[(kg * 8 + 3) * 132];
        float v4 = col[(kg * 8 + 4) * 132], v5 = col[(kg * 8 + 5) * 132];
        float v6 = col[(kg * 8 + 6) * 132], v7 = col[(kg * 8 + 7) * 132];
        __half2 h0 = __floats2half2_rn(v0, v1), h1 = __floats2half2_rn(v2, v3);
        __half2 h2 = __floats2half2_rn(v4, v5), h3 = __floats2half2_rn(v6, v7);
        uint4 u;
        u.x = *reinterpret_cast<uint32_t*>(&h0);
        u.y = *reinterpret_cast<uint32_t*>(&h1);
        u.z = *reinterpret_cast<uint32_t*>(&h2);
        u.w = *reinterpret_cast<uint32_t*>(&h3);
        *reinterpret_cast<uint4*>(Bd + n * 40 + kg * 8) = u;
    }
    __syncthreads();

    for (int kt = 0; kt < 16; kt++) {
        const int a_slot = kt % 3;
        const int bbuf = kt & 1;

        // wait for stage kt+1, transpose it into B[kt+1 & 1] (concurrent with MMA below)
        if (kt <= 13) { CP_WAIT(1); }
        else if (kt == 14) { CP_WAIT(0); }
        if (kt < 15) {
            const int ns = (kt + 1) % 3;
            const float* S = reinterpret_cast<const float*>(smc + K1_SS(ns));
            __half* Bd = reinterpret_cast<__half*>(smc + K1_BS((kt + 1) & 1));
            const int n = tid & 127, kg = tid >> 7;
            const float* col = S + n;
            float v0 = col[(kg * 8 + 0) * 132], v1 = col[(kg * 8 + 1) * 132];
            float v2 = col[(kg * 8 + 2) * 132], v3 = col[(kg * 8 + 3) * 132];
            float v4 = col[(kg * 8 + 4) * 132], v5 = col[(kg * 8 + 5) * 132];
            float v6 = col[(kg * 8 + 6) * 132], v7 = col[(kg * 8 + 7) * 132];
            __half2 h0 = __floats2half2_rn(v0, v1), h1 = __floats2half2_rn(v2, v3);
            __half2 h2 = __floats2half2_rn(v4, v5), h3 = __floats2half2_rn(v6, v7);
            uint4 u;
            u.x = *reinterpret_cast<uint32_t*>(&h0);
            u.y = *reinterpret_cast<uint32_t*>(&h1);
            u.z = *reinterpret_cast<uint32_t*>(&h2);
            u.w = *reinterpret_cast<uint32_t*>(&h3);
            *reinterpret_cast<uint4*>(Bd + n * 40 + kg * 8) = u;
        }

        // MMA on A[a_slot], B[bbuf]
        const uint32_t* A32 = reinterpret_cast<const uint32_t*>(smc + K1_AS(a_slot));
        const uint32_t* B32 = reinterpret_cast<const uint32_t*>(smc + K1_BS(bbuf));
#pragma unroll
        for (int kk = 0; kk < 2; kk++) {
            uint32_t af[3][4], bf[4][2];
#pragma unroll
            for (int mi = 0; mi < 3; mi++) {
                int base = (wm + mi * 16 + gid) * 20 + kk * 8 + tig;
                af[mi][0] = A32[base];
                af[mi][1] = A32[base + 8 * 20];
                af[mi][2] = A32[base + 4];
                af[mi][3] = A32[base + 8 * 20 + 4];
            }
#pragma unroll
            for (int ni = 0; ni < 4; ni++) {
                int base = (wn + ni * 8 + gid) * 20 + kk * 8 + tig;
                bf[ni][0] = B32[base];
                bf[ni][1] = B32[base + 4];
            }
#pragma unroll
            for (int mi = 0; mi < 3; mi++)
#pragma unroll
                for (int ni = 0; ni < 4; ni++) mma16(acc[mi][ni], af[mi], bf[ni]);
        }
        __syncthreads();

        // issue stage kt+3 into the slot just freed (kt % 3)
        if (kt <= 12) {
            const int k0 = (kt + 3) * 32;
            char* Ad = smc + K1_AS(a_slot);
            char* Sd = smc + K1_SS(a_slot);
            {
                int r = av >> 2, kv = av & 3;
                cp_async16(Ad + r * 80 + kv * 16, g_W + (size_t)r * 512 + k0 + kv * 8);
                if (av1 < 768) {
                    int r1 = av1 >> 2, kv1 = av1 & 3;
                    cp_async16(Ad + r1 * 80 + kv1 * 16, g_W + (size_t)r1 * 512 + k0 + kv1 * 8);
                }
            }
#pragma unroll
            for (int i = 0; i < 2; i++) {
                int v = tid + i * 512, k = v >> 5, nv = v & 31;
                cp_async16(Sd + k * 528 + nv * 16, Xb + (size_t)(k0 + k) * NN + n0 + nv * 4);
            }
            CP_COMMIT();
        }
    }

    // ---------------- epilogue ----------------
    __half* bufQ = reinterpret_cast<__half*>(smc);           // [64][136]
    __half* bufK = reinterpret_cast<__half*>(smc + 17408);
    __half* bufV = reinterpret_cast<__half*>(smc + 34816);

#pragma unroll
    for (int mi = 0; mi < 3; mi++) {
        int row = wm + mi * 16;
        int p = row >> 6;
        int lr = (row & 63) + gid;
        const float* bias = p == 0 ? bq : (p == 1 ? bk : bv);
        __half* dst = p == 0 ? bufQ : (p == 1 ? bufK : bufV);
        float b0v = bias[lr], b1v = bias[lr + 8];
#pragma unroll
        for (int ni = 0; ni < 4; ni++) {
            int col = wn + ni * 8 + 2 * tig;
            sth2(dst + lr * 136 + col,       acc[mi][ni][0] + b0v, acc[mi][ni][1] + b0v);
            sth2(dst + (lr + 8) * 136 + col, acc[mi][ni][2] + b1v, acc[mi][ni][3] + b1v);
        }
    }
    __syncthreads();

    // V -> global
#pragma unroll
    for (int i = 0; i < 2; i++) {
        int v = tid + i * 512;
        int row = v >> 4, c = v & 15;
        uint4 t = *reinterpret_cast<const uint4*>(bufV + row * 136 + c * 8);
        *reinterpret_cast<uint4*>(g_V + ((size_t)b * CPD + row) * NN + n0 + c * 8) = t;
    }

    // energy: E(64,64) = K(64x128) @ Q(64x128)^T, 16 warps (4m x 4n)
    {
        const int wmE = (warp & 3) * 16;
        const int wnE = (warp >> 2) * 16;
        float accE[2][4];
#pragma unroll
        for (int j = 0; j < 2; j++)
#pragma unroll
            for (int q = 0; q < 4; q++) accE[j][q] = 0.f;

        const uint32_t* A32 = reinterpret_cast<const uint32_t*>(bufK);
        const uint32_t* B32 = reinterpret_cast<const uint32_t*>(bufQ);
#pragma unroll
        for (int kk = 0; kk < 8; kk++) {
            uint32_t af[4], bf[2][2];
            int base = (wmE + gid) * 68 + kk * 8 + tig;
            af[0] = A32[base];
            af[1] = A32[base + 8 * 68];
            af[2] = A32[base + 4];
            af[3] = A32[base + 8 * 68 + 4];
#pragma unroll
            for (int ni = 0; ni < 2; ni++) {
                int bb = (wnE + ni * 8 + gid) * 68 + kk * 8 + tig;
                bf[ni][0] = B32[bb];
                bf[ni][1] = B32[bb + 4];
            }
#pragma unroll
            for (int ni = 0; ni < 2; ni++) mma16(accE[ni], af, bf[ni]);
        }

        float* P = g_P + (size_t)(b * 32 + blockIdx.x) * CPD * CPD;
        int r0 = wmE + gid;
#pragma unroll
        for (int ni = 0; ni < 2; ni++) {
            int cc = wnE + ni * 8 + 2 * tig;
            *reinterpret_cast<float2*>(P + (size_t)r0 * CPD + cc) =
                make_float2(accE[ni][0], accE[ni][1]);
            *reinterpret_cast<float2*>(P + (size_t)(r0 + 8) * CPD + cc) =
                make_float2(accE[ni][2], accE[ni][3]);
        }
    }
}

// ============================================================================
// K3: reduce 32 partials + softmax + M = Wo @ A (fp32 compute, fp16 store)
// grid (4 cgroups, 16 b), 512 threads
// ============================================================================
__global__ __launch_bounds__(512) void softmax_momix_kernel(const float* __restrict__ wo)
{
    __shared__ float A[64][68];
    __shared__ float Wos[64][68];
    const int cg = blockIdx.x, b = blockIdx.y, tid = threadIdx.x;

    for (int idx = tid; idx < 4096; idx += 512) {
        float ssum = 0.f;
#pragma unroll
        for (int p = 0; p < 32; p++)
            ssum += g_P[(size_t)(b * 32 + p) * 4096 + idx];
        A[idx >> 6][idx & 63] = ssum;
    }
    __syncthreads();
    if (tid < 64) {
        float m = -1e30f;
#pragma unroll
        for (int j = 0; j < 64; j++) m = fmaxf(m, A[tid][j]);
        float ssum = 0.f;
#pragma unroll
        for (int j = 0; j < 64; j++) {
            float e = __expf(A[tid][j] - m);
            A[tid][j] = e;
            ssum += e;
        }
        float inv = 1.f / ssum;
#pragma unroll
        for (int j = 0; j < 64; j++) A[tid][j] *= inv;
    }
    __syncthreads();

    const int cl = tid >> 3, jg = tid & 7;
    for (int ci = 0; ci < 2; ci++) {
        const int c0 = (cg * 2 + ci) * 64;
#pragma unroll
        for (int i = 0; i < 2; i++) {
            int v = tid + i * 512, m = v >> 4, kv = v & 15;
            *reinterpret_cast<float4*>(&Wos[m][kv * 4]) =
                *reinterpret_cast<const float4*>(wo + (size_t)(c0 + m) * CPD + kv * 4);
        }
        __syncthreads();

        float acc[8];
#pragma unroll
        for (int q = 0; q < 8; q++) acc[q] = 0.f;
#pragma unroll 8
        for (int o = 0; o < 64; o++) {
            float w = Wos[cl][o];
            const float4* ar = reinterpret_cast<const float4*>(&A[o][jg * 8]);
            float4 a0 = ar[0], a1 = ar[1];
            acc[0] += w * a0.x; acc[1] += w * a0.y; acc[2] += w * a0.z; acc[3] += w * a0.w;
            acc[4] += w * a1.x; acc[5] += w * a1.y; acc[6] += w * a1.z; acc[7] += w * a1.w;
        }
        __half2 h0 = __floats2half2_rn(acc[0], acc[1]);
        __half2 h1 = __floats2half2_rn(acc[2], acc[3]);
        __half2 h2 = __floats2half2_rn(acc[4], acc[5]);
        __half2 h3 = __floats2half2_rn(acc[6], acc[7]);
        uint4 u;
        u.x = *reinterpret_cast<uint32_t*>(&h0);
        u.y = *reinterpret_cast<uint32_t*>(&h1);
        u.z = *reinterpret_cast<uint32_t*>(&h2);
        u.w = *reinterpret_cast<uint32_t*>(&h3);
        *reinterpret_cast<uint4*>(g_M + ((size_t)b * CC + c0 + cl) * CPD + jg * 8) = u;
        __syncthreads();
    }
}

// ============================================================================
// K4: Y = gamma*(M @ V + bo) + X.  [fp16 mma, smem-staged float4 epilogue]
// grid (32 n-tiles, 16 b, 4 c-quarters), 256 threads (8 warps: 2m x 4n).
// smem bytes: Vt @0 (18432), Ms @18432 (2x9216), Ys fp32 @36864 (33792)
//             Vraw overlays Ys @36864 (17408). Total 70656.
// ============================================================================
#define K4_SMEMB 70656

__global__ __launch_bounds__(256) void out_kernel(
    const float* __restrict__ x, const float* __restrict__ bo,
    const float* __restrict__ gamma, float* __restrict__ y)
{
    extern __shared__ char smc4[];
    __half* Vt = reinterpret_cast<__half*>(smc4);            // [128][72]
    __half* Ms = reinterpret_cast<__half*>(smc4 + 18432);    // [2][64][72]
    float*  Ys = reinterpret_cast<float*>(smc4 + 36864);     // [64][132]
    __half* Vraw = reinterpret_cast<__half*>(smc4 + 36864);  // [64][136] overlay

    const int n0 = blockIdx.x * 128, b = blockIdx.y;
    const int cb = blockIdx.z * 128;
    const int tid = threadIdx.x, lane = tid & 31, warp = tid >> 5;
    const int wm = (warp & 1) * 32, wn = (warp >> 1) * 32;
    const int gid = lane >> 2, tig = lane & 3;

    // group0: Vraw + M chunk 0
#pragma unroll
    for (int i = 0; i < 4; i++) {
        int v = tid + i * 256, r = v >> 4, sg = v & 15;
        cp_async16(Vraw + r * 136 + sg * 8,
                   g_V + ((size_t)b * CPD + r) * NN + n0 + sg * 8);
    }
#pragma unroll
    for (int i = 0; i < 2; i++) {
        int v = tid + i * 256, r = v >> 3, sg = v & 7;
        cp_async16(Ms + r * 72 + sg * 8,
                   g_M + ((size_t)b * CC + cb + r) * CPD + sg * 8);
    }
    CP_COMMIT();
    CP_WAIT(0);
    __syncthreads();

    // transpose Vraw[cp][n] -> Vt[n][cp]
    {
        const int n = tid & 127, cph = tid >> 7;
#pragma unroll
        for (int j = 0; j < 16; j++) {
            int cp = 2 * cph + 4 * j;
            __half a = Vraw[cp * 136 + n];
            __half c = Vraw[(cp + 1) * 136 + n];
            *reinterpret_cast<__half2*>(Vt + n * 72 + cp) = __halves2half2(a, c);
        }
    }
    __syncthreads();

    const float g = gamma[0];

    for (int ch = 0; ch < 2; ch++) {
        const int buf = ch & 1;
        const int c0 = cb + ch * 64;
        if (ch < 1) {
            __half* Md = Ms + 4608;
#pragma unroll
            for (int i = 0; i < 2; i++) {
                int v = tid + i * 256, r = v >> 3, sg = v & 7;
                cp_async16(Md + r * 72 + sg * 8,
                           g_M + ((size_t)b * CC + c0 + 64 + r) * CPD + sg * 8);
            }
            CP_COMMIT();
            CP_WAIT(1);
        } else {
            CP_WAIT(0);
        }
        __syncthreads();

        float acc[2][4][4];
#pragma unroll
        for (int i = 0; i < 2; i++)
#pragma unroll
            for (int j = 0; j < 4; j++)
#pragma unroll
                for (int q = 0; q < 4; q++) acc[i][j][q] = 0.f;

        const uint32_t* A32 = reinterpret_cast<const uint32_t*>(Ms + buf * 4608);
        const uint32_t* B32 = reinterpret_cast<const uint32_t*>(Vt);
#pragma unroll
        for (int kk = 0; kk < 4; kk++) {
            uint32_t af[2][4], bf[4][2];
#pragma unroll
            for (int mi = 0; mi < 2; mi++) {
                int base = (wm + mi * 16 + gid) * 36 + kk * 8 + tig;
                af[mi][0] = A32[base];
                af[mi][1] = A32[base + 8 * 36];
                af[mi][2] = A32[base + 4];
                af[mi][3] = A32[base + 8 * 36 + 4];
            }
#pragma unroll
            for (int ni = 0; ni < 4; ni++) {
                int base = (wn + ni * 8 + gid) * 36 + kk * 8 + tig;
                bf[ni][0] = B32[base];
                bf[ni][1] = B32[base + 4];
            }
#pragma unroll
            for (int mi = 0; mi < 2; mi++)
#pragma unroll
                for (int ni = 0; ni < 4; ni++) mma16(acc[mi][ni], af[mi], bf[ni]);
        }

        // stage gamma*(acc+bo) into Ys
#pragma unroll
        for (int mi = 0; mi < 2; mi++) {
            int r0 = wm + mi * 16 + gid;
            float bo0 = bo[c0 + r0], bo1 = bo[c0 + r0 + 8];
#pragma unroll
            for (int ni = 0; ni < 4; ni++) {
                int col = wn + ni * 8 + 2 * tig;
                *reinterpret_cast<float2*>(Ys + r0 * 132 + col) =
                    make_float2(g * (acc[mi][ni][0] + bo0), g * (acc[mi][ni][1] + bo0));
                *reinterpret_cast<float2*>(Ys + (r0 + 8) * 132 + col) =
                    make_float2(g * (acc[mi][ni][2] + bo1), g * (acc[mi][ni][3] + bo1));
            }
        }
        __syncthreads();

        // linear float4 pass: Y = Ys + X
#pragma unroll
        for (int i = 0; i < 8; i++) {
            int v = tid + i * 256;              // 0..2047
            int row = v >> 5, c4 = (v & 31) * 4;
            size_t off = ((size_t)b * CC + c0 + row) * NN + n0 + c4;
            float4 xv = *reinterpret_cast<const float4*>(x + off);
            float4 yv = *reinterpret_cast<const float4*>(Ys + row * 132 + c4);
            yv.x += xv.x; yv.y += xv.y; yv.z += xv.z; yv.w += xv.w;
            *reinterpret_cast<float4*>(y + off) = yv;
        }
        __syncthreads();
    }
}

// ============================================================================
extern "C" void kernel_launch(void* const* d_in, const int* in_sizes, int n_in,
                              void* d_out, int out_size)
{
    const float* x  = (const float*)d_in[0];
    const float* wq = (const float*)d_in[1];
    const float* bq = (const float*)d_in[2];
    const float* wk = (const float*)d_in[3];
    const float* bk = (const float*)d_in[4];
    const float* wv = (const float*)d_in[5];
    const float* bv = (const float*)d_in[6];
    const float* wo = (const float*)d_in[7];
    const float* bo = (const float*)d_in[8];
    const float* gm = (const float*)d_in[9];
    float* y = (float*)d_out;

    static int inited = 0;
    if (!inited) {
        cudaFuncSetAttribute(qkv_energy_kernel, cudaFuncAttributeMaxDynamicSharedMemorySize,
                             K1_SMEMB);
        cudaFuncSetAttribute(out_kernel, cudaFuncAttributeMaxDynamicSharedMemorySize,
                             K4_SMEMB);
        inited = 1;
    }

    wconv_kernel<<<96, 256>>>(wq, wk, wv);
    qkv_energy_kernel<<<dim3(32, 16), 512, K1_SMEMB>>>(x, bq, bk, bv);
    softmax_momix_kernel<<<dim3(4, 16), 512>>>(wo);
    out_kernel<<<dim3(32, 16, 4), 256, K4_SMEMB>>>(x, bo, gm, y);
}

// round 8
// speedup vs baseline: 1.5969x; 1.0221x over previous
#include <cuda_runtime.h>
#include <cuda_fp16.h>
#include <cstdint>

#define NB 16
#define CC 512
#define CPD 64
#define NN 4096

// scratch (static __device__ — no allocation)
__device__ __half g_V[(size_t)NB * CPD * NN];
__device__ float  g_P[(size_t)NB * 32 * CPD * CPD]; // energy partials (32 n-slices)
__device__ __half g_M[NB * CC * CPD];               // M = Wo @ A (fp16)
__device__ __half g_W[192 * 512];                   // fp16 Wqkv

__device__ __forceinline__ void cp_async16(void* smem, const void* gmem) {
    uint32_t s = (uint32_t)__cvta_generic_to_shared(smem);
    asm volatile("cp.async.cg.shared.global [%0], [%1], 16;\n" :: "r"(s), "l"(gmem));
}
#define CP_COMMIT() asm volatile("cp.async.commit_group;\n" ::: "memory")
#define CP_WAIT(n)  asm volatile("cp.async.wait_group %0;\n" :: "n"(n) : "memory")

__device__ __forceinline__ void mma16(float c[4], const uint32_t a[4], const uint32_t b[2]) {
    asm volatile(
        "mma.sync.aligned.m16n8k16.row.col.f32.f16.f16.f32 "
        "{%0,%1,%2,%3},{%4,%5,%6,%7},{%8,%9},{%0,%1,%2,%3};"
        : "+f"(c[0]), "+f"(c[1]), "+f"(c[2]), "+f"(c[3])
        : "r"(a[0]), "r"(a[1]), "r"(a[2]), "r"(a[3]), "r"(b[0]), "r"(b[1]));
}

__device__ __forceinline__ void sth2(__half* p, float a, float b) {
    *reinterpret_cast<__half2*>(p) = __floats2half2_rn(a, b);
}

// ============================================================================
// K0: convert Wqkv -> fp16 g_W. grid 96, 256 threads
// ============================================================================
__global__ __launch_bounds__(256) void wconv_kernel(
    const float* __restrict__ wq, const float* __restrict__ wk, const float* __restrict__ wv)
{
    int f = (blockIdx.x * 256 + threadIdx.x) * 4;
    int r = f >> 9, c = f & 511;
    const float* w = r < 64 ? wq + (size_t)r * 512
                   : r < 128 ? wk + (size_t)(r - 64) * 512
                             : wv + (size_t)(r - 128) * 512;
    float4 t = *reinterpret_cast<const float4*>(w + c);
    __half2 h0 = __floats2half2_rn(t.x, t.y);
    __half2 h1 = __floats2half2_rn(t.z, t.w);
    uint2 u;
    u.x = *reinterpret_cast<uint32_t*>(&h0);
    u.y = *reinterpret_cast<uint32_t*>(&h1);
    *reinterpret_cast<uint2*>(g_W + (size_t)r * 512 + c) = u;
}

// ============================================================================
// K1: fused QKV + energy. 512 threads (16 warps: 4m x 4n), tile 192x128, BK=64
// Triple-buffered A/S (cp.async), double-buffered B (transposed fp16 X).
// Per iter: CP_WAIT -> __syncthreads (race-safe) -> {transpose(kt+1) | MMA(kt)}
//           -> __syncthreads -> issue stage kt+3.
// byte offsets: A slots @0,27648,55296 (192x72 halves)
//               S slots @82944,116736,150528 (64x132 fp32)
//               B0 @184320, B1 @202752 (128x72 halves). total 221184
// epilogue overlay: bufQ @0, bufK @17408, bufV @34816 (each 64x136 halves)
// ============================================================================
#define K1_AS(i) ((i) * 27648)
#define K1_SS(i) (82944 + (i) * 33792)
#define K1_BS(i) (184320 + (i) * 18432)
#define K1_SMEMB 221184

__device__ __forceinline__ void k1_transpose(const char* smc, int s_slot, int b_buf, int tid) {
    const float* S = reinterpret_cast<const float*>(smc + K1_SS(s_slot));
    __half* Bd = reinterpret_cast<__half*>(const_cast<char*>(smc) + K1_BS(b_buf));
    const int n = tid & 127, kg = tid >> 7;       // kg 0..3, 16 k-rows each
    const float* col = S + n;
#pragma unroll
    for (int j2 = 0; j2 < 2; j2++) {
        int kb = kg * 16 + j2 * 8;
        float v0 = col[(kb + 0) * 132], v1 = col[(kb + 1) * 132];
        float v2 = col[(kb + 2) * 132], v3 = col[(kb + 3) * 132];
        float v4 = col[(kb + 4) * 132], v5 = col[(kb + 5) * 132];
        float v6 = col[(kb + 6) * 132], v7 = col[(kb + 7) * 132];
        __half2 h0 = __floats2half2_rn(v0, v1), h1 = __floats2half2_rn(v2, v3);
        __half2 h2 = __floats2half2_rn(v4, v5), h3 = __floats2half2_rn(v6, v7);
        uint4 u;
        u.x = *reinterpret_cast<uint32_t*>(&h0);
        u.y = *reinterpret_cast<uint32_t*>(&h1);
        u.z = *reinterpret_cast<uint32_t*>(&h2);
        u.w = *reinterpret_cast<uint32_t*>(&h3);
        *reinterpret_cast<uint4*>(Bd + n * 72 + kb) = u;
    }
}

__device__ __forceinline__ void k1_issue_stage(char* smc, int slot, int k0,
                                               const float* Xb, int n0, int tid) {
    char* Ad = smc + K1_AS(slot);
    char* Sd = smc + K1_SS(slot);
#pragma unroll
    for (int i = 0; i < 3; i++) {                // 1536 cp of A (192x64 halves)
        int v = tid + i * 512, r = v >> 3, kv = v & 7;
        cp_async16(Ad + r * 144 + kv * 16, g_W + (size_t)r * 512 + k0 + kv * 8);
    }
#pragma unroll
    for (int i = 0; i < 4; i++) {                // 2048 cp of S (64x128 fp32)
        int v = tid + i * 512, k = v >> 5, nv = v & 31;
        cp_async16(Sd + k * 528 + nv * 16, Xb + (size_t)(k0 + k) * NN + n0 + nv * 4);
    }
    CP_COMMIT();
}

__global__ __launch_bounds__(512, 1) void qkv_energy_kernel(
    const float* __restrict__ x,
    const float* __restrict__ bq, const float* __restrict__ bk, const float* __restrict__ bv)
{
    extern __shared__ char smc[];
    const int b = blockIdx.y;
    const int n0 = blockIdx.x * 128;
    const float* Xb = x + (size_t)b * CC * NN;

    const int tid = threadIdx.x;
    const int lane = tid & 31, warp = tid >> 5;
    const int wm = (warp & 3) * 48;
    const int wn = (warp >> 2) * 32;
    const int gid = lane >> 2, tig = lane & 3;

    float acc[3][4][4];
#pragma unroll
    for (int i = 0; i < 3; i++)
#pragma unroll
        for (int j = 0; j < 4; j++)
#pragma unroll
            for (int q = 0; q < 4; q++) acc[i][j][q] = 0.f;

    // prologue: issue stages 0,1,2
    k1_issue_stage(smc, 0, 0, Xb, n0, tid);
    k1_issue_stage(smc, 1, 64, Xb, n0, tid);
    k1_issue_stage(smc, 2, 128, Xb, n0, tid);
    CP_WAIT(2);              // stage 0 landed (this thread)
    __syncthreads();         // all threads' stage-0 copies visible
    k1_transpose(smc, 0, 0, tid);
    __syncthreads();

    for (int kt = 0; kt < 8; kt++) {
        const int a_slot = kt % 3;
        const int bbuf = kt & 1;

        if (kt <= 5) { CP_WAIT(1); }             // stage kt+1 landed
        else if (kt == 6) { CP_WAIT(0); }
        __syncthreads();                         // make copies visible to ALL

        // transpose stage kt+1 (disjoint buffers) runs with MMA on stage kt
        if (kt < 7) k1_transpose(smc, (kt + 1) % 3, (kt + 1) & 1, tid);

        const uint32_t* A32 = reinterpret_cast<const uint32_t*>(smc + K1_AS(a_slot));
        const uint32_t* B32 = reinterpret_cast<const uint32_t*>(smc + K1_BS(bbuf));
#pragma unroll
        for (int kk = 0; kk < 4; kk++) {
            uint32_t af[3][4], bf[4][2];
#pragma unroll
            for (int mi = 0; mi < 3; mi++) {
                int base = (wm + mi * 16 + gid) * 36 + kk * 8 + tig;
                af[mi][0] = A32[base];
                af[mi][1] = A32[base + 8 * 36];
                af[mi][2] = A32[base + 4];
                af[mi][3] = A32[base + 8 * 36 + 4];
            }
#pragma unroll
            for (int ni = 0; ni < 4; ni++) {
                int base = (wn + ni * 8 + gid) * 36 + kk * 8 + tig;
                bf[ni][0] = B32[base];
                bf[ni][1] = B32[base + 4];
            }
#pragma unroll
            for (int mi = 0; mi < 3; mi++)
#pragma unroll
                for (int ni = 0; ni < 4; ni++) mma16(acc[mi][ni], af[mi], bf[ni]);
        }
        __syncthreads();                         // A[a_slot]/S[a_slot]/B free

        if (kt <= 4)                             // stage kt+3
            k1_issue_stage(smc, a_slot, (kt + 3) * 64, Xb, n0, tid);
    }

    // ---------------- epilogue ----------------
    __half* bufQ = reinterpret_cast<__half*>(smc);           // [64][136]
    __half* bufK = reinterpret_cast<__half*>(smc + 17408);
    __half* bufV = reinterpret_cast<__half*>(smc + 34816);

#pragma unroll
    for (int mi = 0; mi < 3; mi++) {
        int row = wm + mi * 16;
        int p = row >> 6;
        int lr = (row & 63) + gid;
        const float* bias = p == 0 ? bq : (p == 1 ? bk : bv);
        __half* dst = p == 0 ? bufQ : (p == 1 ? bufK : bufV);
        float b0v = bias[lr], b1v = bias[lr + 8];
#pragma unroll
        for (int ni = 0; ni < 4; ni++) {
            int col = wn + ni * 8 + 2 * tig;
            sth2(dst + lr * 136 + col,       acc[mi][ni][0] + b0v, acc[mi][ni][1] + b0v);
            sth2(dst + (lr + 8) * 136 + col, acc[mi][ni][2] + b1v, acc[mi][ni][3] + b1v);
        }
    }
    __syncthreads();

    // V -> global
#pragma unroll
    for (int i = 0; i < 2; i++) {
        int v = tid + i * 512;
        int row = v >> 4, c = v & 15;
        uint4 t = *reinterpret_cast<const uint4*>(bufV + row * 136 + c * 8);
        *reinterpret_cast<uint4*>(g_V + ((size_t)b * CPD + row) * NN + n0 + c * 8) = t;
    }

    // energy: E(64,64) = K(64x128) @ Q(64x128)^T, 16 warps (4m x 4n)
    {
        const int wmE = (warp & 3) * 16;
        const int wnE = (warp >> 2) * 16;
        float accE[2][4];
#pragma unroll
        for (int j = 0; j < 2; j++)
#pragma unroll
            for (int q = 0; q < 4; q++) accE[j][q] = 0.f;

        const uint32_t* A32 = reinterpret_cast<const uint32_t*>(bufK);
        const uint32_t* B32 = reinterpret_cast<const uint32_t*>(bufQ);
#pragma unroll
        for (int kk = 0; kk < 8; kk++) {
            uint32_t af[4], bf[2][2];
            int base = (wmE + gid) * 68 + kk * 8 + tig;
            af[0] = A32[base];
            af[1] = A32[base + 8 * 68];
            af[2] = A32[base + 4];
            af[3] = A32[base + 8 * 68 + 4];
#pragma unroll
            for (int ni = 0; ni < 2; ni++) {
                int bb = (wnE + ni * 8 + gid) * 68 + kk * 8 + tig;
                bf[ni][0] = B32[bb];
                bf[ni][1] = B32[bb + 4];
            }
#pragma unroll
            for (int ni = 0; ni < 2; ni++) mma16(accE[ni], af, bf[ni]);
        }

        float* P = g_P + (size_t)(b * 32 + blockIdx.x) * CPD * CPD;
        int r0 = wmE + gid;
#pragma unroll
        for (int ni = 0; ni < 2; ni++) {
            int cc = wnE + ni * 8 + 2 * tig;
            *reinterpret_cast<float2*>(P + (size_t)r0 * CPD + cc) =
                make_float2(accE[ni][0], accE[ni][1]);
            *reinterpret_cast<float2*>(P + (size_t)(r0 + 8) * CPD + cc) =
                make_float2(accE[ni][2], accE[ni][3]);
        }
    }
}

// ============================================================================
// K3: reduce 32 partials + softmax + M = Wo @ A (fp32 compute, fp16 store)
// grid (4 cgroups, 16 b), 512 threads
// ============================================================================
__global__ __launch_bounds__(512) void softmax_momix_kernel(const float* __restrict__ wo)
{
    __shared__ float A[64][68];
    __shared__ float Wos[64][68];
    const int cg = blockIdx.x, b = blockIdx.y, tid = threadIdx.x;

    for (int idx = tid; idx < 4096; idx += 512) {
        float ssum = 0.f;
#pragma unroll
        for (int p = 0; p < 32; p++)
            ssum += g_P[(size_t)(b * 32 + p) * 4096 + idx];
        A[idx >> 6][idx & 63] = ssum;
    }
    __syncthreads();
    if (tid < 64) {
        float m = -1e30f;
#pragma unroll
        for (int j = 0; j < 64; j++) m = fmaxf(m, A[tid][j]);
        float ssum = 0.f;
#pragma unroll
        for (int j = 0; j < 64; j++) {
            float e = __expf(A[tid][j] - m);
            A[tid][j] = e;
            ssum += e;
        }
        float inv = 1.f / ssum;
#pragma unroll
        for (int j = 0; j < 64; j++) A[tid][j] *= inv;
    }
    __syncthreads();

    const int cl = tid >> 3, jg = tid & 7;
    for (int ci = 0; ci < 2; ci++) {
        const int c0 = (cg * 2 + ci) * 64;
#pragma unroll
        for (int i = 0; i < 2; i++) {
            int v = tid + i * 512, m = v >> 4, kv = v & 15;
            *reinterpret_cast<float4*>(&Wos[m][kv * 4]) =
                *reinterpret_cast<const float4*>(wo + (size_t)(c0 + m) * CPD + kv * 4);
        }
        __syncthreads();

        float acc[8];
#pragma unroll
        for (int q = 0; q < 8; q++) acc[q] = 0.f;
#pragma unroll 8
        for (int o = 0; o < 64; o++) {
            float w = Wos[cl][o];
            const float4* ar = reinterpret_cast<const float4*>(&A[o][jg * 8]);
            float4 a0 = ar[0], a1 = ar[1];
            acc[0] += w * a0.x; acc[1] += w * a0.y; acc[2] += w * a0.z; acc[3] += w * a0.w;
            acc[4] += w * a1.x; acc[5] += w * a1.y; acc[6] += w * a1.z; acc[7] += w * a1.w;
        }
        __half2 h0 = __floats2half2_rn(acc[0], acc[1]);
        __half2 h1 = __floats2half2_rn(acc[2], acc[3]);
        __half2 h2 = __floats2half2_rn(acc[4], acc[5]);
        __half2 h3 = __floats2half2_rn(acc[6], acc[7]);
        uint4 u;
        u.x = *reinterpret_cast<uint32_t*>(&h0);
        u.y = *reinterpret_cast<uint32_t*>(&h1);
        u.z = *reinterpret_cast<uint32_t*>(&h2);
        u.w = *reinterpret_cast<uint32_t*>(&h3);
        *reinterpret_cast<uint4*>(g_M + ((size_t)b * CC + c0 + cl) * CPD + jg * 8) = u;
        __syncthreads();
    }
}

// ============================================================================
// K4: Y = gamma*(M @ V + bo) + X.  [fp16 mma, smem-staged float4 epilogue]
// grid (32 n-tiles, 16 b, 4 c-quarters), 256 threads (8 warps: 2m x 4n).
// ============================================================================
#define K4_SMEMB 70656

__global__ __launch_bounds__(256) void out_kernel(
    const float* __restrict__ x, const float* __restrict__ bo,
    const float* __restrict__ gamma, float* __restrict__ y)
{
    extern __shared__ char smc4[];
    __half* Vt = reinterpret_cast<__half*>(smc4);            // [128][72]
    __half* Ms = reinterpret_cast<__half*>(smc4 + 18432);    // [2][64][72]
    float*  Ys = reinterpret_cast<float*>(smc4 + 36864);     // [64][132]
    __half* Vraw = reinterpret_cast<__half*>(smc4 + 36864);  // [64][136] overlay

    const int n0 = blockIdx.x * 128, b = blockIdx.y;
    const int cb = blockIdx.z * 128;
    const int tid = threadIdx.x, lane = tid & 31, warp = tid >> 5;
    const int wm = (warp & 1) * 32, wn = (warp >> 1) * 32;
    const int gid = lane >> 2, tig = lane & 3;

#pragma unroll
    for (int i = 0; i < 4; i++) {
        int v = tid + i * 256, r = v >> 4, sg = v & 15;
        cp_async16(Vraw + r * 136 + sg * 8,
                   g_V + ((size_t)b * CPD + r) * NN + n0 + sg * 8);
    }
#pragma unroll
    for (int i = 0; i < 2; i++) {
        int v = tid + i * 256, r = v >> 3, sg = v & 7;
        cp_async16(Ms + r * 72 + sg * 8,
                   g_M + ((size_t)b * CC + cb + r) * CPD + sg * 8);
    }
    CP_COMMIT();
    CP_WAIT(0);
    __syncthreads();

    {
        const int n = tid & 127, cph = tid >> 7;
#pragma unroll
        for (int j = 0; j < 16; j++) {
            int cp = 2 * cph + 4 * j;
            __half a = Vraw[cp * 136 + n];
            __half c = Vraw[(cp + 1) * 136 + n];
            *reinterpret_cast<__half2*>(Vt + n * 72 + cp) = __halves2half2(a, c);
        }
    }
    __syncthreads();

    const float g = gamma[0];

    for (int ch = 0; ch < 2; ch++) {
        const int buf = ch & 1;
        const int c0 = cb + ch * 64;
        if (ch < 1) {
            __half* Md = Ms + 4608;
#pragma unroll
            for (int i = 0; i < 2; i++) {
                int v = tid + i * 256, r = v >> 3, sg = v & 7;
                cp_async16(Md + r * 72 + sg * 8,
                           g_M + ((size_t)b * CC + c0 + 64 + r) * CPD + sg * 8);
            }
            CP_COMMIT();
            CP_WAIT(1);
        } else {
            CP_WAIT(0);
        }
        __syncthreads();

        float acc[2][4][4];
#pragma unroll
        for (int i = 0; i < 2; i++)
#pragma unroll
            for (int j = 0; j < 4; j++)
#pragma unroll
                for (int q = 0; q < 4; q++) acc[i][j][q] = 0.f;

        const uint32_t* A32 = reinterpret_cast<const uint32_t*>(Ms + buf * 4608);
        const uint32_t* B32 = reinterpret_cast<const uint32_t*>(Vt);
#pragma unroll
        for (int kk = 0; kk < 4; kk++) {
            uint32_t af[2][4], bf[4][2];
#pragma unroll
            for (int mi = 0; mi < 2; mi++) {
                int base = (wm + mi * 16 + gid) * 36 + kk * 8 + tig;
                af[mi][0] = A32[base];
                af[mi][1] = A32[base + 8 * 36];
                af[mi][2] = A32[base + 4];
                af[mi][3] = A32[base + 8 * 36 + 4];
            }
#pragma unroll
            for (int ni = 0; ni < 4; ni++) {
                int base = (wn + ni * 8 + gid) * 36 + kk * 8 + tig;
                bf[ni][0] = B32[base];
                bf[ni][1] = B32[base + 4];
            }
#pragma unroll
            for (int mi = 0; mi < 2; mi++)
#pragma unroll
                for (int ni = 0; ni < 4; ni++) mma16(acc[mi][ni], af[mi], bf[ni]);
        }

#pragma unroll
        for (int mi = 0; mi < 2; mi++) {
            int r0 = wm + mi * 16 + gid;
            float bo0 = bo[c0 + r0], bo1 = bo[c0 + r0 + 8];
#pragma unroll
            for (int ni = 0; ni < 4; ni++) {
                int col = wn + ni * 8 + 2 * tig;
                *reinterpret_cast<float2*>(Ys + r0 * 132 + col) =
                    make_float2(g * (acc[mi][ni][0] + bo0), g * (acc[mi][ni][1] + bo0));
                *reinterpret_cast<float2*>(Ys + (r0 + 8) * 132 + col) =
                    make_float2(g * (acc[mi][ni][2] + bo1), g * (acc[mi][ni][3] + bo1));
            }
        }
        __syncthreads();

#pragma unroll
        for (int i = 0; i < 8; i++) {
            int v = tid + i * 256;
            int row = v >> 5, c4 = (v & 31) * 4;
            size_t off = ((size_t)b * CC + c0 + row) * NN + n0 + c4;
            float4 xv = *reinterpret_cast<const float4*>(x + off);
            float4 yv = *reinterpret_cast<const float4*>(Ys + row * 132 + c4);
            yv.x += xv.x; yv.y += xv.y; yv.z += xv.z; yv.w += xv.w;
            *reinterpret_cast<float4*>(y + off) = yv;
        }
        __syncthreads();
    }
}

// ============================================================================
extern "C" void kernel_launch(void* const* d_in, const int* in_sizes, int n_in,
                              void* d_out, int out_size)
{
    const float* x  = (const float*)d_in[0];
    const float* wq = (const float*)d_in[1];
    const float* bq = (const float*)d_in[2];
    const float* wk = (const float*)d_in[3];
    const float* bk = (const float*)d_in[4];
    const float* wv = (const float*)d_in[5];
    const float* bv = (const float*)d_in[6];
    const float* wo = (const float*)d_in[7];
    const float* bo = (const float*)d_in[8];
    const float* gm = (const float*)d_in[9];
    float* y = (float*)d_out;

    static int inited = 0;
    if (!inited) {
        cudaFuncSetAttribute(qkv_energy_kernel, cudaFuncAttributeMaxDynamicSharedMemorySize,
                             K1_SMEMB);
        cudaFuncSetAttribute(out_kernel, cudaFuncAttributeMaxDynamicSharedMemorySize,
                             K4_SMEMB);
        inited = 1;
    }

    wconv_kernel<<<96, 256>>>(wq, wk, wv);
    qkv_energy_kernel<<<dim3(32, 16), 512, K1_SMEMB>>>(x, bq, bk, bv);
    softmax_momix_kernel<<<dim3(4, 16), 512>>>(wo);
    out_kernel<<<dim3(32, 16, 4), 256, K4_SMEMB>>>(x, bo, gm, y);
}

// round 9
// speedup vs baseline: 1.6241x; 1.0170x over previous
#include <cuda_runtime.h>
#include <cuda_fp16.h>
#include <cstdint>

#define NB 16
#define CC 512
#define CPD 64
#define NN 4096

// scratch (static __device__ — no allocation)
__device__ __half g_V[(size_t)NB * CPD * NN];
__device__ float  g_P[(size_t)NB * 32 * CPD * CPD]; // energy partials (32 n-slices)
__device__ __half g_M[NB * CC * CPD];               // M = Wo @ A (fp16)
__device__ __half g_W[192 * 512];                   // fp16 Wqkv

__device__ __forceinline__ void cp_async16(void* smem, const void* gmem) {
    uint32_t s = (uint32_t)__cvta_generic_to_shared(smem);
    asm volatile("cp.async.cg.shared.global [%0], [%1], 16;\n" :: "r"(s), "l"(gmem));
}
#define CP_COMMIT() asm volatile("cp.async.commit_group;\n" ::: "memory")
#define CP_WAIT(n)  asm volatile("cp.async.wait_group %0;\n" :: "n"(n) : "memory")

__device__ __forceinline__ void mma16(float c[4], const uint32_t a[4], const uint32_t b[2]) {
    asm volatile(
        "mma.sync.aligned.m16n8k16.row.col.f32.f16.f16.f32 "
        "{%0,%1,%2,%3},{%4,%5,%6,%7},{%8,%9},{%0,%1,%2,%3};"
        : "+f"(c[0]), "+f"(c[1]), "+f"(c[2]), "+f"(c[3])
        : "r"(a[0]), "r"(a[1]), "r"(a[2]), "r"(a[3]), "r"(b[0]), "r"(b[1]));
}

// ldmatrix x4: one 16x16 fp16 tile -> 4 fragment regs (conflict-free @144B stride)
__device__ __forceinline__ void ldsm_x4(uint32_t r[4], uint32_t smaddr) {
    asm volatile("ldmatrix.sync.aligned.m8n8.x4.shared.b16 {%0,%1,%2,%3}, [%4];"
        : "=r"(r[0]), "=r"(r[1]), "=r"(r[2]), "=r"(r[3]) : "r"(smaddr));
}

__device__ __forceinline__ void sth2(__half* p, float a, float b) {
    *reinterpret_cast<__half2*>(p) = __floats2half2_rn(a, b);
}

// ============================================================================
// K0: convert Wqkv -> fp16 g_W. grid 96, 256 threads
// ============================================================================
__global__ __launch_bounds__(256) void wconv_kernel(
    const float* __restrict__ wq, const float* __restrict__ wk, const float* __restrict__ wv)
{
    int f = (blockIdx.x * 256 + threadIdx.x) * 4;
    int r = f >> 9, c = f & 511;
    const float* w = r < 64 ? wq + (size_t)r * 512
                   : r < 128 ? wk + (size_t)(r - 64) * 512
                             : wv + (size_t)(r - 128) * 512;
    float4 t = *reinterpret_cast<const float4*>(w + c);
    __half2 h0 = __floats2half2_rn(t.x, t.y);
    __half2 h1 = __floats2half2_rn(t.z, t.w);
    uint2 u;
    u.x = *reinterpret_cast<uint32_t*>(&h0);
    u.y = *reinterpret_cast<uint32_t*>(&h1);
    *reinterpret_cast<uint2*>(g_W + (size_t)r * 512 + c) = u;
}

// ============================================================================
// K1: fused QKV + energy. 512 threads (16 warps: 4m x 4n), tile 192x128, BK=64
// Triple-buffered A/S (cp.async), double-buffered B; ldmatrix fragment loads.
// ============================================================================
#define K1_AS(i) ((i) * 27648)
#define K1_SS(i) (82944 + (i) * 33792)
#define K1_BS(i) (184320 + (i) * 18432)
#define K1_SMEMB 221184

__device__ __forceinline__ void k1_transpose(const char* smc, int s_slot, int b_buf, int tid) {
    const float* S = reinterpret_cast<const float*>(smc + K1_SS(s_slot));
    __half* Bd = reinterpret_cast<__half*>(const_cast<char*>(smc) + K1_BS(b_buf));
    const int n = tid & 127, kg = tid >> 7;       // kg 0..3, 16 k-rows each
    const float* col = S + n;
#pragma unroll
    for (int j2 = 0; j2 < 2; j2++) {
        int kb = kg * 16 + j2 * 8;
        float v0 = col[(kb + 0) * 132], v1 = col[(kb + 1) * 132];
        float v2 = col[(kb + 2) * 132], v3 = col[(kb + 3) * 132];
        float v4 = col[(kb + 4) * 132], v5 = col[(kb + 5) * 132];
        float v6 = col[(kb + 6) * 132], v7 = col[(kb + 7) * 132];
        __half2 h0 = __floats2half2_rn(v0, v1), h1 = __floats2half2_rn(v2, v3);
        __half2 h2 = __floats2half2_rn(v4, v5), h3 = __floats2half2_rn(v6, v7);
        uint4 u;
        u.x = *reinterpret_cast<uint32_t*>(&h0);
        u.y = *reinterpret_cast<uint32_t*>(&h1);
        u.z = *reinterpret_cast<uint32_t*>(&h2);
        u.w = *reinterpret_cast<uint32_t*>(&h3);
        *reinterpret_cast<uint4*>(Bd + n * 72 + kb) = u;
    }
}

__device__ __forceinline__ void k1_issue_stage(char* smc, int slot, int k0,
                                               const float* Xb, int n0, int tid) {
    char* Ad = smc + K1_AS(slot);
    char* Sd = smc + K1_SS(slot);
#pragma unroll
    for (int i = 0; i < 3; i++) {                // 1536 cp of A (192x64 halves)
        int v = tid + i * 512, r = v >> 3, kv = v & 7;
        cp_async16(Ad + r * 144 + kv * 16, g_W + (size_t)r * 512 + k0 + kv * 8);
    }
#pragma unroll
    for (int i = 0; i < 4; i++) {                // 2048 cp of S (64x128 fp32)
        int v = tid + i * 512, k = v >> 5, nv = v & 31;
        cp_async16(Sd + k * 528 + nv * 16, Xb + (size_t)(k0 + k) * NN + n0 + nv * 4);
    }
    CP_COMMIT();
}

__global__ __launch_bounds__(512, 1) void qkv_energy_kernel(
    const float* __restrict__ x,
    const float* __restrict__ bq, const float* __restrict__ bk, const float* __restrict__ bv)
{
    extern __shared__ char smc[];
    const int b = blockIdx.y;
    const int n0 = blockIdx.x * 128;
    const float* Xb = x + (size_t)b * CC * NN;

    const int tid = threadIdx.x;
    const int lane = tid & 31, warp = tid >> 5;
    const int wm = (warp & 3) * 48;
    const int wn = (warp >> 2) * 32;
    const int gid = lane >> 2, tig = lane & 3;
    const int lrow = lane & 15;                  // ldmatrix row provider
    const int lkb = (lane >> 4) * 16;            // ldmatrix k-half offset (bytes)

    float acc[3][4][4];
#pragma unroll
    for (int i = 0; i < 3; i++)
#pragma unroll
        for (int j = 0; j < 4; j++)
#pragma unroll
            for (int q = 0; q < 4; q++) acc[i][j][q] = 0.f;

    // prologue: issue stages 0,1,2
    k1_issue_stage(smc, 0, 0, Xb, n0, tid);
    k1_issue_stage(smc, 1, 64, Xb, n0, tid);
    k1_issue_stage(smc, 2, 128, Xb, n0, tid);
    CP_WAIT(2);
    __syncthreads();
    k1_transpose(smc, 0, 0, tid);
    __syncthreads();

    const uint32_t smcBase = (uint32_t)__cvta_generic_to_shared(smc);

    for (int kt = 0; kt < 8; kt++) {
        const int a_slot = kt % 3;
        const int bbuf = kt & 1;

        if (kt <= 5) { CP_WAIT(1); }
        else if (kt == 6) { CP_WAIT(0); }
        __syncthreads();

        if (kt < 7) k1_transpose(smc, (kt + 1) % 3, (kt + 1) & 1, tid);

        const uint32_t aBase = smcBase + K1_AS(a_slot);
        const uint32_t bBase = smcBase + K1_BS(bbuf);
#pragma unroll
        for (int kk = 0; kk < 4; kk++) {
            uint32_t af[3][4], bt[2][4];
#pragma unroll
            for (int mi = 0; mi < 3; mi++)
                ldsm_x4(af[mi], aBase + (wm + mi * 16 + lrow) * 144 + kk * 32 + lkb);
#pragma unroll
            for (int t = 0; t < 2; t++)
                ldsm_x4(bt[t], bBase + (wn + t * 16 + lrow) * 144 + kk * 32 + lkb);
#pragma unroll
            for (int mi = 0; mi < 3; mi++)
#pragma unroll
                for (int ni = 0; ni < 4; ni++) {
                    uint32_t bb[2] = { bt[ni >> 1][ni & 1], bt[ni >> 1][(ni & 1) + 2] };
                    mma16(acc[mi][ni], af[mi], bb);
                }
        }
        __syncthreads();

        if (kt <= 4)
            k1_issue_stage(smc, a_slot, (kt + 3) * 64, Xb, n0, tid);
    }

    // ---------------- epilogue ----------------
    __half* bufQ = reinterpret_cast<__half*>(smc);           // [64][136]
    __half* bufK = reinterpret_cast<__half*>(smc + 17408);
    __half* bufV = reinterpret_cast<__half*>(smc + 34816);

#pragma unroll
    for (int mi = 0; mi < 3; mi++) {
        int row = wm + mi * 16;
        int p = row >> 6;
        int lr = (row & 63) + gid;
        const float* bias = p == 0 ? bq : (p == 1 ? bk : bv);
        __half* dst = p == 0 ? bufQ : (p == 1 ? bufK : bufV);
        float b0v = bias[lr], b1v = bias[lr + 8];
#pragma unroll
        for (int ni = 0; ni < 4; ni++) {
            int col = wn + ni * 8 + 2 * tig;
            sth2(dst + lr * 136 + col,       acc[mi][ni][0] + b0v, acc[mi][ni][1] + b0v);
            sth2(dst + (lr + 8) * 136 + col, acc[mi][ni][2] + b1v, acc[mi][ni][3] + b1v);
        }
    }
    __syncthreads();

    // V -> global
#pragma unroll
    for (int i = 0; i < 2; i++) {
        int v = tid + i * 512;
        int row = v >> 4, c = v & 15;
        uint4 t = *reinterpret_cast<const uint4*>(bufV + row * 136 + c * 8);
        *reinterpret_cast<uint4*>(g_V + ((size_t)b * CPD + row) * NN + n0 + c * 8) = t;
    }

    // energy: E(64,64) = K(64x128) @ Q(64x128)^T, 16 warps (4m x 4n)
    {
        const int wmE = (warp & 3) * 16;
        const int wnE = (warp >> 2) * 16;
        float accE[2][4];
#pragma unroll
        for (int j = 0; j < 2; j++)
#pragma unroll
            for (int q = 0; q < 4; q++) accE[j][q] = 0.f;

        const uint32_t* A32 = reinterpret_cast<const uint32_t*>(bufK);
        const uint32_t* B32 = reinterpret_cast<const uint32_t*>(bufQ);
#pragma unroll
        for (int kk = 0; kk < 8; kk++) {
            uint32_t af[4], bf[2][2];
            int base = (wmE + gid) * 68 + kk * 8 + tig;
            af[0] = A32[base];
            af[1] = A32[base + 8 * 68];
            af[2] = A32[base + 4];
            af[3] = A32[base + 8 * 68 + 4];
#pragma unroll
            for (int ni = 0; ni < 2; ni++) {
                int bb = (wnE + ni * 8 + gid) * 68 + kk * 8 + tig;
                bf[ni][0] = B32[bb];
                bf[ni][1] = B32[bb + 4];
            }
#pragma unroll
            for (int ni = 0; ni < 2; ni++) mma16(accE[ni], af, bf[ni]);
        }

        float* P = g_P + (size_t)(b * 32 + blockIdx.x) * CPD * CPD;
        int r0 = wmE + gid;
#pragma unroll
        for (int ni = 0; ni < 2; ni++) {
            int cc = wnE + ni * 8 + 2 * tig;
            *reinterpret_cast<float2*>(P + (size_t)r0 * CPD + cc) =
                make_float2(accE[ni][0], accE[ni][1]);
            *reinterpret_cast<float2*>(P + (size_t)(r0 + 8) * CPD + cc) =
                make_float2(accE[ni][2], accE[ni][3]);
        }
    }
}

// ============================================================================
// K3: reduce 32 partials + softmax + M = Wo @ A (fp32 compute, fp16 store)
// grid (4 cgroups, 16 b), 512 threads
// ============================================================================
__global__ __launch_bounds__(512) void softmax_momix_kernel(const float* __restrict__ wo)
{
    __shared__ float A[64][68];
    __shared__ float Wos[64][68];
    const int cg = blockIdx.x, b = blockIdx.y, tid = threadIdx.x;

    for (int idx = tid; idx < 4096; idx += 512) {
        float ssum = 0.f;
#pragma unroll
        for (int p = 0; p < 32; p++)
            ssum += g_P[(size_t)(b * 32 + p) * 4096 + idx];
        A[idx >> 6][idx & 63] = ssum;
    }
    __syncthreads();
    if (tid < 64) {
        float m = -1e30f;
#pragma unroll
        for (int j = 0; j < 64; j++) m = fmaxf(m, A[tid][j]);
        float ssum = 0.f;
#pragma unroll
        for (int j = 0; j < 64; j++) {
            float e = __expf(A[tid][j] - m);
            A[tid][j] = e;
            ssum += e;
        }
        float inv = 1.f / ssum;
#pragma unroll
        for (int j = 0; j < 64; j++) A[tid][j] *= inv;
    }
    __syncthreads();

    const int cl = tid >> 3, jg = tid & 7;
    for (int ci = 0; ci < 2; ci++) {
        const int c0 = (cg * 2 + ci) * 64;
#pragma unroll
        for (int i = 0; i < 2; i++) {
            int v = tid + i * 512, m = v >> 4, kv = v & 15;
            *reinterpret_cast<float4*>(&Wos[m][kv * 4]) =
                *reinterpret_cast<const float4*>(wo + (size_t)(c0 + m) * CPD + kv * 4);
        }
        __syncthreads();

        float acc[8];
#pragma unroll
        for (int q = 0; q < 8; q++) acc[q] = 0.f;
#pragma unroll 8
        for (int o = 0; o < 64; o++) {
            float w = Wos[cl][o];
            const float4* ar = reinterpret_cast<const float4*>(&A[o][jg * 8]);
            float4 a0 = ar[0], a1 = ar[1];
            acc[0] += w * a0.x; acc[1] += w * a0.y; acc[2] += w * a0.z; acc[3] += w * a0.w;
            acc[4] += w * a1.x; acc[5] += w * a1.y; acc[6] += w * a1.z; acc[7] += w * a1.w;
        }
        __half2 h0 = __floats2half2_rn(acc[0], acc[1]);
        __half2 h1 = __floats2half2_rn(acc[2], acc[3]);
        __half2 h2 = __floats2half2_rn(acc[4], acc[5]);
        __half2 h3 = __floats2half2_rn(acc[6], acc[7]);
        uint4 u;
        u.x = *reinterpret_cast<uint32_t*>(&h0);
        u.y = *reinterpret_cast<uint32_t*>(&h1);
        u.z = *reinterpret_cast<uint32_t*>(&h2);
        u.w = *reinterpret_cast<uint32_t*>(&h3);
        *reinterpret_cast<uint4*>(g_M + ((size_t)b * CC + c0 + cl) * CPD + jg * 8) = u;
        __syncthreads();
    }
}

// ============================================================================
// K4: Y = gamma*(M @ V + bo) + X.  [fp16 mma + ldmatrix, float4 epilogue]
// grid (32 n-tiles, 16 b, 4 c-quarters), 256 threads (8 warps: 2m x 4n).
// ============================================================================
#define K4_SMEMB 70656

__global__ __launch_bounds__(256) void out_kernel(
    const float* __restrict__ x, const float* __restrict__ bo,
    const float* __restrict__ gamma, float* __restrict__ y)
{
    extern __shared__ char smc4[];
    __half* Vt = reinterpret_cast<__half*>(smc4);            // [128][72]
    __half* Ms = reinterpret_cast<__half*>(smc4 + 18432);    // [2][64][72]
    float*  Ys = reinterpret_cast<float*>(smc4 + 36864);     // [64][132]
    __half* Vraw = reinterpret_cast<__half*>(smc4 + 36864);  // [64][136] overlay

    const int n0 = blockIdx.x * 128, b = blockIdx.y;
    const int cb = blockIdx.z * 128;
    const int tid = threadIdx.x, lane = tid & 31, warp = tid >> 5;
    const int wm = (warp & 1) * 32, wn = (warp >> 1) * 32;
    const int gid = lane >> 2, tig = lane & 3;
    const int lrow = lane & 15, lkb = (lane >> 4) * 16;

#pragma unroll
    for (int i = 0; i < 4; i++) {
        int v = tid + i * 256, r = v >> 4, sg = v & 15;
        cp_async16(Vraw + r * 136 + sg * 8,
                   g_V + ((size_t)b * CPD + r) * NN + n0 + sg * 8);
    }
#pragma unroll
    for (int i = 0; i < 2; i++) {
        int v = tid + i * 256, r = v >> 3, sg = v & 7;
        cp_async16(Ms + r * 72 + sg * 8,
                   g_M + ((size_t)b * CC + cb + r) * CPD + sg * 8);
    }
    CP_COMMIT();
    CP_WAIT(0);
    __syncthreads();

    {
        const int n = tid & 127, cph = tid >> 7;
#pragma unroll
        for (int j = 0; j < 16; j++) {
            int cp = 2 * cph + 4 * j;
            __half a = Vraw[cp * 136 + n];
            __half c = Vraw[(cp + 1) * 136 + n];
            *reinterpret_cast<__half2*>(Vt + n * 72 + cp) = __halves2half2(a, c);
        }
    }
    __syncthreads();

    const float g = gamma[0];
    const uint32_t vtBase = (uint32_t)__cvta_generic_to_shared(Vt);
    const uint32_t msBase = (uint32_t)__cvta_generic_to_shared(Ms);

    for (int ch = 0; ch < 2; ch++) {
        const int buf = ch & 1;
        const int c0 = cb + ch * 64;
        if (ch < 1) {
            __half* Md = Ms + 4608;
#pragma unroll
            for (int i = 0; i < 2; i++) {
                int v = tid + i * 256, r = v >> 3, sg = v & 7;
                cp_async16(Md + r * 72 + sg * 8,
                           g_M + ((size_t)b * CC + c0 + 64 + r) * CPD + sg * 8);
            }
            CP_COMMIT();
            CP_WAIT(1);
        } else {
            CP_WAIT(0);
        }
        __syncthreads();

        float acc[2][4][4];
#pragma unroll
        for (int i = 0; i < 2; i++)
#pragma unroll
            for (int j = 0; j < 4; j++)
#pragma unroll
                for (int q = 0; q < 4; q++) acc[i][j][q] = 0.f;

        const uint32_t aBase = msBase + buf * 9216;
#pragma unroll
        for (int kk = 0; kk < 4; kk++) {
            uint32_t af[2][4], bt[2][4];
#pragma unroll
            for (int mi = 0; mi < 2; mi++)
                ldsm_x4(af[mi], aBase + (wm + mi * 16 + lrow) * 144 + kk * 32 + lkb);
#pragma unroll
            for (int t = 0; t < 2; t++)
                ldsm_x4(bt[t], vtBase + (wn + t * 16 + lrow) * 144 + kk * 32 + lkb);
#pragma unroll
            for (int mi = 0; mi < 2; mi++)
#pragma unroll
                for (int ni = 0; ni < 4; ni++) {
                    uint32_t bb[2] = { bt[ni >> 1][ni & 1], bt[ni >> 1][(ni & 1) + 2] };
                    mma16(acc[mi][ni], af[mi], bb);
                }
        }

#pragma unroll
        for (int mi = 0; mi < 2; mi++) {
            int r0 = wm + mi * 16 + gid;
            float bo0 = bo[c0 + r0], bo1 = bo[c0 + r0 + 8];
#pragma unroll
            for (int ni = 0; ni < 4; ni++) {
                int col = wn + ni * 8 + 2 * tig;
                *reinterpret_cast<float2*>(Ys + r0 * 132 + col) =
                    make_float2(g * (acc[mi][ni][0] + bo0), g * (acc[mi][ni][1] + bo0));
                *reinterpret_cast<float2*>(Ys + (r0 + 8) * 132 + col) =
                    make_float2(g * (acc[mi][ni][2] + bo1), g * (acc[mi][ni][3] + bo1));
            }
        }
        __syncthreads();

#pragma unroll
        for (int i = 0; i < 8; i++) {
            int v = tid + i * 256;
            int row = v >> 5, c4 = (v & 31) * 4;
            size_t off = ((size_t)b * CC + c0 + row) * NN + n0 + c4;
            float4 xv = *reinterpret_cast<const float4*>(x + off);
            float4 yv = *reinterpret_cast<const float4*>(Ys + row * 132 + c4);
            yv.x += xv.x; yv.y += xv.y; yv.z += xv.z; yv.w += xv.w;
            *reinterpret_cast<float4*>(y + off) = yv;
        }
        __syncthreads();
    }
}

// ============================================================================
extern "C" void kernel_launch(void* const* d_in, const int* in_sizes, int n_in,
                              void* d_out, int out_size)
{
    const float* x  = (const float*)d_in[0];
    const float* wq = (const float*)d_in[1];
    const float* bq = (const float*)d_in[2];
    const float* wk = (const float*)d_in[3];
    const float* bk = (const float*)d_in[4];
    const float* wv = (const float*)d_in[5];
    const float* bv = (const float*)d_in[6];
    const float* wo = (const float*)d_in[7];
    const float* bo = (const float*)d_in[8];
    const float* gm = (const float*)d_in[9];
    float* y = (float*)d_out;

    static int inited = 0;
    if (!inited) {
        cudaFuncSetAttribute(qkv_energy_kernel, cudaFuncAttributeMaxDynamicSharedMemorySize,
                             K1_SMEMB);
        cudaFuncSetAttribute(out_kernel, cudaFuncAttributeMaxDynamicSharedMemorySize,
                             K4_SMEMB);
        inited = 1;
    }

    wconv_kernel<<<96, 256>>>(wq, wk, wv);
    qkv_energy_kernel<<<dim3(32, 16), 512, K1_SMEMB>>>(x, bq, bk, bv);
    softmax_momix_kernel<<<dim3(4, 16), 512>>>(wo);
    out_kernel<<<dim3(32, 16, 4), 256, K4_SMEMB>>>(x, bo, gm, y);
}

// round 11
// speedup vs baseline: 1.6389x; 1.0091x over previous
#include <cuda_runtime.h>
#include <cuda_fp16.h>
#include <cstdint>

#define NB 16
#define CC 512
#define CPD 64
#define NN 4096

// scratch (static __device__ — no allocation)
__device__ __half g_V[(size_t)NB * CPD * NN];
__device__ float  g_P[(size_t)NB * 64 * CPD * CPD]; // energy partials (64 n-slices)
__device__ __half g_M[NB * CC * CPD];               // M = Wo @ A (fp16)
__device__ __half g_W[192 * 512];                   // fp16 Wqkv

__device__ __forceinline__ void cp_async16(void* smem, const void* gmem) {
    uint32_t s = (uint32_t)__cvta_generic_to_shared(smem);
    asm volatile("cp.async.cg.shared.global [%0], [%1], 16;\n" :: "r"(s), "l"(gmem));
}
#define CP_COMMIT() asm volatile("cp.async.commit_group;\n" ::: "memory")
#define CP_WAIT(n)  asm volatile("cp.async.wait_group %0;\n" :: "n"(n) : "memory")

__device__ __forceinline__ void mma16(float c[4], const uint32_t a[4], const uint32_t b[2]) {
    asm volatile(
        "mma.sync.aligned.m16n8k16.row.col.f32.f16.f16.f32 "
        "{%0,%1,%2,%3},{%4,%5,%6,%7},{%8,%9},{%0,%1,%2,%3};"
        : "+f"(c[0]), "+f"(c[1]), "+f"(c[2]), "+f"(c[3])
        : "r"(a[0]), "r"(a[1]), "r"(a[2]), "r"(a[3]), "r"(b[0]), "r"(b[1]));
}

__device__ __forceinline__ void ldsm_x4(uint32_t r[4], uint32_t smaddr) {
    asm volatile("ldmatrix.sync.aligned.m8n8.x4.shared.b16 {%0,%1,%2,%3}, [%4];"
        : "=r"(r[0]), "=r"(r[1]), "=r"(r[2]), "=r"(r[3]) : "r"(smaddr));
}

__device__ __forceinline__ void sth2(__half* p, float a, float b) {
    *reinterpret_cast<__half2*>(p) = __floats2half2_rn(a, b);
}

// ============================================================================
// K0: convert Wqkv -> fp16 g_W. grid 96, 256 threads
// ============================================================================
__global__ __launch_bounds__(256) void wconv_kernel(
    const float* __restrict__ wq, const float* __restrict__ wk, const float* __restrict__ wv)
{
    int f = (blockIdx.x * 256 + threadIdx.x) * 4;
    int r = f >> 9, c = f & 511;
    const float* w = r < 64 ? wq + (size_t)r * 512
                   : r < 128 ? wk + (size_t)(r - 64) * 512
                             : wv + (size_t)(r - 128) * 512;
    float4 t = *reinterpret_cast<const float4*>(w + c);
    __half2 h0 = __floats2half2_rn(t.x, t.y);
    __half2 h1 = __floats2half2_rn(t.z, t.w);
    uint2 u;
    u.x = *reinterpret_cast<uint32_t*>(&h0);
    u.y = *reinterpret_cast<uint32_t*>(&h1);
    *reinterpret_cast<uint2*>(g_W + (size_t)r * 512 + c) = u;
}

// ============================================================================
// K1: fused QKV + energy. 256 threads (8 warps: 4m x 2n), tile 192x64, BK=32,
// 16 iters, triple-buffered A/S, double-buffered B. 2 CTAs/SM.
//   A slot: [192][40]h (80B row, 16B-aligned)  @ 0,15360,30720
//   S slot: [32][68]f  (272B row)              @ 46080,54784,63488
//   B buf : [64][40]h  (80B row)               @ 72192,77312
// epilogue overlay: bufQ @0, bufK @9216, bufV @18432 (each [64][72]h, 144B row)
// ============================================================================
#define K1_AS(i) ((i) * 15360)
#define K1_SS(i) (46080 + (i) * 8704)
#define K1_BS(i) (72192 + (i) * 5120)
#define K1_SMEMB 82432

__device__ __forceinline__ void k1_transpose(char* smc, int s_slot, int b_buf, int tid) {
    const float* S = reinterpret_cast<const float*>(smc + K1_SS(s_slot));
    __half* Bd = reinterpret_cast<__half*>(smc + K1_BS(b_buf));
    const int n = tid & 63, kb = (tid >> 6) * 8;   // 4 k-groups of 8
    const float* col = S + n;
    float v0 = col[(kb + 0) * 68], v1 = col[(kb + 1) * 68];
    float v2 = col[(kb + 2) * 68], v3 = col[(kb + 3) * 68];
    float v4 = col[(kb + 4) * 68], v5 = col[(kb + 5) * 68];
    float v6 = col[(kb + 6) * 68], v7 = col[(kb + 7) * 68];
    __half2 h0 = __floats2half2_rn(v0, v1), h1 = __floats2half2_rn(v2, v3);
    __half2 h2 = __floats2half2_rn(v4, v5), h3 = __floats2half2_rn(v6, v7);
    uint4 u;
    u.x = *reinterpret_cast<uint32_t*>(&h0);
    u.y = *reinterpret_cast<uint32_t*>(&h1);
    u.z = *reinterpret_cast<uint32_t*>(&h2);
    u.w = *reinterpret_cast<uint32_t*>(&h3);
    *reinterpret_cast<uint4*>(Bd + n * 40 + kb) = u;
}

__device__ __forceinline__ void k1_issue_stage(char* smc, int slot, int k0,
                                               const float* Xb, int n0, int tid) {
    char* Ad = smc + K1_AS(slot);
    char* Sd = smc + K1_SS(slot);
#pragma unroll
    for (int i = 0; i < 3; i++) {                // 768 cp of A (192x32 halves)
        int v = tid + i * 256, r = v >> 2, kv = v & 3;
        cp_async16(Ad + r * 80 + kv * 16, g_W + (size_t)r * 512 + k0 + kv * 8);
    }
#pragma unroll
    for (int i = 0; i < 2; i++) {                // 512 cp of S (32x64 fp32)
        int v = tid + i * 256, k = v >> 4, nv = v & 15;
        cp_async16(Sd + k * 272 + nv * 16, Xb + (size_t)(k0 + k) * NN + n0 + nv * 4);
    }
    CP_COMMIT();
}

__global__ __launch_bounds__(256, 2) void qkv_energy_kernel(
    const float* __restrict__ x,
    const float* __restrict__ bq, const float* __restrict__ bk, const float* __restrict__ bv)
{
    extern __shared__ char smc[];
    const int b = blockIdx.y;
    const int n0 = blockIdx.x * 64;
    const float* Xb = x + (size_t)b * CC * NN;

    const int tid = threadIdx.x;
    const int lane = tid & 31, warp = tid >> 5;
    const int wm = (warp & 3) * 48;              // m-offset in 192
    const int wn = (warp >> 2) * 32;             // n-offset in 64
    const int gid = lane >> 2, tig = lane & 3;
    const int lrow = lane & 15, lkb = (lane >> 4) * 16;

    float acc[3][4][4];
#pragma unroll
    for (int i = 0; i < 3; i++)
#pragma unroll
        for (int j = 0; j < 4; j++)
#pragma unroll
            for (int q = 0; q < 4; q++) acc[i][j][q] = 0.f;

    // prologue
    k1_issue_stage(smc, 0, 0, Xb, n0, tid);
    k1_issue_stage(smc, 1, 32, Xb, n0, tid);
    k1_issue_stage(smc, 2, 64, Xb, n0, tid);
    CP_WAIT(2);
    __syncthreads();
    k1_transpose(smc, 0, 0, tid);
    __syncthreads();

    const uint32_t smcBase = (uint32_t)__cvta_generic_to_shared(smc);

    for (int kt = 0; kt < 16; kt++) {
        const int a_slot = kt % 3;
        const int bbuf = kt & 1;

        if (kt <= 13) { CP_WAIT(1); }            // stage kt+1 landed (this thread)
        else if (kt == 14) { CP_WAIT(0); }
        __syncthreads();                         // visible to all threads

        if (kt < 15) k1_transpose(smc, (kt + 1) % 3, (kt + 1) & 1, tid);

        const uint32_t aBase = smcBase + K1_AS(a_slot);
        const uint32_t bBase = smcBase + K1_BS(bbuf);
#pragma unroll
        for (int kk = 0; kk < 2; kk++) {
            uint32_t af[3][4], bt[2][4];
#pragma unroll
            for (int mi = 0; mi < 3; mi++)
                ldsm_x4(af[mi], aBase + (wm + mi * 16 + lrow) * 80 + kk * 32 + lkb);
#pragma unroll
            for (int t = 0; t < 2; t++)
                ldsm_x4(bt[t], bBase + (wn + t * 16 + lrow) * 80 + kk * 32 + lkb);
#pragma unroll
            for (int mi = 0; mi < 3; mi++)
#pragma unroll
                for (int ni = 0; ni < 4; ni++) {
                    uint32_t bb[2] = { bt[ni >> 1][ni & 1], bt[ni >> 1][(ni & 1) + 2] };
                    mma16(acc[mi][ni], af[mi], bb);
                }
        }
        __syncthreads();                         // frag reads done; slot reusable

        if (kt <= 12)
            k1_issue_stage(smc, a_slot, (kt + 3) * 32, Xb, n0, tid);
    }

    // ---------------- epilogue ----------------
    __half* bufQ = reinterpret_cast<__half*>(smc);           // [64][72]
    __half* bufK = reinterpret_cast<__half*>(smc + 9216);
    __half* bufV = reinterpret_cast<__half*>(smc + 18432);

#pragma unroll
    for (int mi = 0; mi < 3; mi++) {
        int row = wm + mi * 16;
        int p = row >> 6;
        int lr = (row & 63) + gid;
        const float* bias = p == 0 ? bq : (p == 1 ? bk : bv);
        __half* dst = p == 0 ? bufQ : (p == 1 ? bufK : bufV);
        float b0v = bias[lr], b1v = bias[lr + 8];
#pragma unroll
        for (int ni = 0; ni < 4; ni++) {
            int col = wn + ni * 8 + 2 * tig;
            sth2(dst + lr * 72 + col,       acc[mi][ni][0] + b0v, acc[mi][ni][1] + b0v);
            sth2(dst + (lr + 8) * 72 + col, acc[mi][ni][2] + b1v, acc[mi][ni][3] + b1v);
        }
    }
    __syncthreads();

    // V -> global
#pragma unroll
    for (int i = 0; i < 2; i++) {
        int v = tid + i * 256;
        int row = v >> 3, c = v & 7;
        uint4 t = *reinterpret_cast<const uint4*>(bufV + row * 72 + c * 8);
        *reinterpret_cast<uint4*>(g_V + ((size_t)b * CPD + row) * NN + n0 + c * 8) = t;
    }

    // energy: E(64,64) = K(64ch x 64n) @ Q(64ch x 64n)^T, 8 warps (4m x 2n)
    {
        const int wmE = (warp & 3) * 16;
        const int wnE = (warp >> 2) * 32;
        const uint32_t kBase = smcBase + 9216;   // bufK
        const uint32_t qBase = smcBase;          // bufQ
        float accE[4][4];
#pragma unroll
        for (int j = 0; j < 4; j++)
#pragma unroll
            for (int q = 0; q < 4; q++) accE[j][q] = 0.f;

#pragma unroll
        for (int kk = 0; kk < 4; kk++) {
            uint32_t af[4], bt[2][4];
            ldsm_x4(af, kBase + (wmE + lrow) * 144 + kk * 32 + lkb);
#pragma unroll
            for (int t = 0; t < 2; t++)
                ldsm_x4(bt[t], qBase + (wnE + t * 16 + lrow) * 144 + kk * 32 + lkb);
#pragma unroll
            for (int ni = 0; ni < 4; ni++) {
                uint32_t bb[2] = { bt[ni >> 1][ni & 1], bt[ni >> 1][(ni & 1) + 2] };
                mma16(accE[ni], af, bb);
            }
        }

        float* P = g_P + (size_t)(b * 64 + blockIdx.x) * CPD * CPD;
        int r0 = wmE + gid;
#pragma unroll
        for (int ni = 0; ni < 4; ni++) {
            int cc = wnE + ni * 8 + 2 * tig;
            *reinterpret_cast<float2*>(P + (size_t)r0 * CPD + cc) =
                make_float2(accE[ni][0], accE[ni][1]);
            *reinterpret_cast<float2*>(P + (size_t)(r0 + 8) * CPD + cc) =
                make_float2(accE[ni][2], accE[ni][3]);
        }
    }
}

// ============================================================================
// K3: reduce 64 partials + softmax + M = Wo @ A (fp32 compute, fp16 store)
// grid (4 cgroups, 16 b), 512 threads
// ============================================================================
__global__ __launch_bounds__(512) void softmax_momix_kernel(const float* __restrict__ wo)
{
    __shared__ float A[64][68];
    __shared__ float Wos[64][68];
    const int cg = blockIdx.x, b = blockIdx.y, tid = threadIdx.x;

    for (int idx = tid; idx < 4096; idx += 512) {
        float ssum = 0.f;
#pragma unroll
        for (int p = 0; p < 64; p++)
            ssum += g_P[(size_t)(b * 64 + p) * 4096 + idx];
        A[idx >> 6][idx & 63] = ssum;
    }
    __syncthreads();
    if (tid < 64) {
        float m = -1e30f;
#pragma unroll
        for (int j = 0; j < 64; j++) m = fmaxf(m, A[tid][j]);
        float ssum = 0.f;
#pragma unroll
        for (int j = 0; j < 64; j++) {
            float e = __expf(A[tid][j] - m);
            A[tid][j] = e;
            ssum += e;
        }
        float inv = 1.f / ssum;
#pragma unroll
        for (int j = 0; j < 64; j++) A[tid][j] *= inv;
    }
    __syncthreads();

    const int cl = tid >> 3, jg = tid & 7;
    for (int ci = 0; ci < 2; ci++) {
        const int c0 = (cg * 2 + ci) * 64;
#pragma unroll
        for (int i = 0; i < 2; i++) {
            int v = tid + i * 512, m = v >> 4, kv = v & 15;
            *reinterpret_cast<float4*>(&Wos[m][kv * 4]) =
                *reinterpret_cast<const float4*>(wo + (size_t)(c0 + m) * CPD + kv * 4);
        }
        __syncthreads();

        float acc[8];
#pragma unroll
        for (int q = 0; q < 8; q++) acc[q] = 0.f;
#pragma unroll 8
        for (int o = 0; o < 64; o++) {
            float w = Wos[cl][o];
            const float4* ar = reinterpret_cast<const float4*>(&A[o][jg * 8]);
            float4 a0 = ar[0], a1 = ar[1];
            acc[0] += w * a0.x; acc[1] += w * a0.y; acc[2] += w * a0.z; acc[3] += w * a0.w;
            acc[4] += w * a1.x; acc[5] += w * a1.y; acc[6] += w * a1.z; acc[7] += w * a1.w;
        }
        __half2 h0 = __floats2half2_rn(acc[0], acc[1]);
        __half2 h1 = __floats2half2_rn(acc[2], acc[3]);
        __half2 h2 = __floats2half2_rn(acc[4], acc[5]);
        __half2 h3 = __floats2half2_rn(acc[6], acc[7]);
        uint4 u;
        u.x = *reinterpret_cast<uint32_t*>(&h0);
        u.y = *reinterpret_cast<uint32_t*>(&h1);
        u.z = *reinterpret_cast<uint32_t*>(&h2);
        u.w = *reinterpret_cast<uint32_t*>(&h3);
        *reinterpret_cast<uint4*>(g_M + ((size_t)b * CC + c0 + cl) * CPD + jg * 8) = u;
        __syncthreads();
    }
}

// ============================================================================
// K4: Y = gamma*(M @ V + bo) + X.  [fp16 mma + ldmatrix, float4 epilogue]
// grid (32 n-tiles, 16 b, 4 c-quarters), 256 threads (8 warps: 2m x 4n).
// ============================================================================
#define K4_SMEMB 70656

__global__ __launch_bounds__(256) void out_kernel(
    const float* __restrict__ x, const float* __restrict__ bo,
    const float* __restrict__ gamma, float* __restrict__ y)
{
    extern __shared__ char smc4[];
    __half* Vt = reinterpret_cast<__half*>(smc4);            // [128][72]
    __half* Ms = reinterpret_cast<__half*>(smc4 + 18432);    // [2][64][72]
    float*  Ys = reinterpret_cast<float*>(smc4 + 36864);     // [64][132]
    __half* Vraw = reinterpret_cast<__half*>(smc4 + 36864);  // [64][136] overlay

    const int n0 = blockIdx.x * 128, b = blockIdx.y;
    const int cb = blockIdx.z * 128;
    const int tid = threadIdx.x, lane = tid & 31, warp = tid >> 5;
    const int wm = (warp & 1) * 32, wn = (warp >> 1) * 32;
    const int gid = lane >> 2, tig = lane & 3;
    const int lrow = lane & 15, lkb = (lane >> 4) * 16;

#pragma unroll
    for (int i = 0; i < 4; i++) {
        int v = tid + i * 256, r = v >> 4, sg = v & 15;
        cp_async16(Vraw + r * 136 + sg * 8,
                   g_V + ((size_t)b * CPD + r) * NN + n0 + sg * 8);
    }
#pragma unroll
    for (int i = 0; i < 2; i++) {
        int v = tid + i * 256, r = v >> 3, sg = v & 7;
        cp_async16(Ms + r * 72 + sg * 8,
                   g_M + ((size_t)b * CC + cb + r) * CPD + sg * 8);
    }
    CP_COMMIT();
    CP_WAIT(0);
    __syncthreads();

    {
        const int n = tid & 127, cph = tid >> 7;
#pragma unroll
        for (int j = 0; j < 16; j++) {
            int cp = 2 * cph + 4 * j;
            __half a = Vraw[cp * 136 + n];
            __half c = Vraw[(cp + 1) * 136 + n];
            *reinterpret_cast<__half2*>(Vt + n * 72 + cp) = __halves2half2(a, c);
        }
    }
    __syncthreads();

    const float g = gamma[0];
    const uint32_t vtBase = (uint32_t)__cvta_generic_to_shared(Vt);
    const uint32_t msBase = (uint32_t)__cvta_generic_to_shared(Ms);

    for (int ch = 0; ch < 2; ch++) {
        const int buf = ch & 1;
        const int c0 = cb + ch * 64;
        if (ch < 1) {
            __half* Md = Ms + 4608;
#pragma unroll
            for (int i = 0; i < 2; i++) {
                int v = tid + i * 256, r = v >> 3, sg = v & 7;
                cp_async16(Md + r * 72 + sg * 8,
                           g_M + ((size_t)b * CC + c0 + 64 + r) * CPD + sg * 8);
            }
            CP_COMMIT();
            CP_WAIT(1);
        } else {
            CP_WAIT(0);
        }
        __syncthreads();

        float acc[2][4][4];
#pragma unroll
        for (int i = 0; i < 2; i++)
#pragma unroll
            for (int j = 0; j < 4; j++)
#pragma unroll
                for (int q = 0; q < 4; q++) acc[i][j][q] = 0.f;

        const uint32_t aBase = msBase + buf * 9216;
#pragma unroll
        for (int kk = 0; kk < 4; kk++) {
            uint32_t af[2][4], bt[2][4];
#pragma unroll
            for (int mi = 0; mi < 2; mi++)
                ldsm_x4(af[mi], aBase + (wm + mi * 16 + lrow) * 144 + kk * 32 + lkb);
#pragma unroll
            for (int t = 0; t < 2; t++)
                ldsm_x4(bt[t], vtBase + (wn + t * 16 + lrow) * 144 + kk * 32 + lkb);
#pragma unroll
            for (int mi = 0; mi < 2; mi++)
#pragma unroll
                for (int ni = 0; ni < 4; ni++) {
                    uint32_t bb[2] = { bt[ni >> 1][ni & 1], bt[ni >> 1][(ni & 1) + 2] };
                    mma16(acc[mi][ni], af[mi], bb);
                }
        }

#pragma unroll
        for (int mi = 0; mi < 2; mi++) {
            int r0 = wm + mi * 16 + gid;
            float bo0 = bo[c0 + r0], bo1 = bo[c0 + r0 + 8];
#pragma unroll
            for (int ni = 0; ni < 4; ni++) {
                int col = wn + ni * 8 + 2 * tig;
                *reinterpret_cast<float2*>(Ys + r0 * 132 + col) =
                    make_float2(g * (acc[mi][ni][0] + bo0), g * (acc[mi][ni][1] + bo0));
                *reinterpret_cast<float2*>(Ys + (r0 + 8) * 132 + col) =
                    make_float2(g * (acc[mi][ni][2] + bo1), g * (acc[mi][ni][3] + bo1));
            }
        }
        __syncthreads();

#pragma unroll
        for (int i = 0; i < 8; i++) {
            int v = tid + i * 256;
            int row = v >> 5, c4 = (v & 31) * 4;
            size_t off = ((size_t)b * CC + c0 + row) * NN + n0 + c4;
            float4 xv = *reinterpret_cast<const float4*>(x + off);
            float4 yv = *reinterpret_cast<const float4*>(Ys + row * 132 + c4);
            yv.x += xv.x; yv.y += xv.y; yv.z += xv.z; yv.w += xv.w;
            *reinterpret_cast<float4*>(y + off) = yv;
        }
        __syncthreads();
    }
}

// ============================================================================
extern "C" void kernel_launch(void* const* d_in, const int* in_sizes, int n_in,
                              void* d_out, int out_size)
{
    const float* x  = (const float*)d_in[0];
    const float* wq = (const float*)d_in[1];
    const float* bq = (const float*)d_in[2];
    const float* wk = (const float*)d_in[3];
    const float* bk = (const float*)d_in[4];
    const float* wv = (const float*)d_in[5];
    const float* bv = (const float*)d_in[6];
    const float* wo = (const float*)d_in[7];
    const float* bo = (const float*)d_in[8];
    const float* gm = (const float*)d_in[9];
    float* y = (float*)d_out;

    static int inited = 0;
    if (!inited) {
        cudaFuncSetAttribute(qkv_energy_kernel, cudaFuncAttributeMaxDynamicSharedMemorySize,
                             K1_SMEMB);
        cudaFuncSetAttribute(out_kernel, cudaFuncAttributeMaxDynamicSharedMemorySize,
                             K4_SMEMB);
        inited = 1;
    }

    wconv_kernel<<<96, 256>>>(wq, wk, wv);
    qkv_energy_kernel<<<dim3(64, 16), 256, K1_SMEMB>>>(x, bq, bk, bv);
    softmax_momix_kernel<<<dim3(4, 16), 512>>>(wo);
    out_kernel<<<dim3(32, 16, 4), 256, K4_SMEMB>>>(x, bo, gm, y);
}